// round 8
// baseline (speedup 1.0000x reference)
#include <cuda_runtime.h>

#define BB 8
#define TT 2560
#define FF 229
#define C1N 5
#define C2N 11
#define F2 114
#define F3 57
#define FEAT 627       // C2N * F3
#define FEATP 640      // padded K (float4-aligned)
#define OFN 88
#define NQKV 144
#define MCN 48
#define GN 8
#define DH 6
#define KW 31
#define PADW 15
#define BNEPS 1e-5f
#define FRAME_ELEMS (BB*TT*OFN)

// ---------------- scratch (device globals; no allocation allowed) ----------
__device__ float g_y1[(size_t)BB*C1N*TT*FF];     // conv1 out  (B,C1,T,F)
__device__ float g_y2[(size_t)BB*C1N*TT*F2];     // conv2+pool (B,C1,T,F2)
__device__ float g_x627[(size_t)BB*TT*FEATP];    // conv3+pool, (B*T, 640) padded
__device__ float g_w2[(size_t)NQKV*FEATP];       // folded W2 = Wqkv @ fc_w  (144, 640)
__device__ float g_b2[NQKV];                     // folded bias = Wqkv @ fc_b
__device__ float g_qkv[(size_t)BB*TT*NQKV];      // q|k|v (B*T, 144)
__device__ float g_out48[(size_t)BB*TT*MCN];     // attention out (B*T, 48)

// ---------------- K0: fold fc into qkv:  W2[n,k] = sum_j Wqkv[n,j]*fc_w[j,k]
// 9 blocks x 256 threads; block = 16 rows of W2
__global__ void k_prep_w2(const float* __restrict__ wq, const float* __restrict__ wk,
                          const float* __restrict__ wv, const float* __restrict__ fcw,
                          const float* __restrict__ fcb) {
    __shared__ float sq[16*OFN];
    int n0 = blockIdx.x * 16;
    for (int i = threadIdx.x; i < 16*OFN; i += 256) {
        int n = n0 + i / OFN, j = i % OFN;
        const float* src = (n < 48) ? (wq + n*OFN) : (n < 96) ? (wk + (n-48)*OFN)
                                                              : (wv + (n-96)*OFN);
        sq[i] = src[j];
    }
    __syncthreads();
    if (threadIdx.x < 16) {
        float s = 0.f;
        for (int j = 0; j < OFN; j++) s += sq[threadIdx.x*OFN + j] * fcb[j];
        g_b2[n0 + threadIdx.x] = s;
    }
    for (int k = threadIdx.x; k < FEATP; k += 256) {
        float acc[16];
        #pragma unroll
        for (int i = 0; i < 16; i++) acc[i] = 0.f;
        if (k < FEAT) {
            for (int j = 0; j < OFN; j++) {
                float f = fcw[j*FEAT + k];
                #pragma unroll
                for (int i = 0; i < 16; i++) acc[i] = fmaf(sq[i*OFN + j], f, acc[i]);
            }
        }
        #pragma unroll
        for (int i = 0; i < 16; i++) g_w2[(size_t)(n0 + i)*FEATP + k] = acc[i];
    }
}

// ---------------- K1: conv1(1->5) + BN + ReLU ------------------------------
__global__ void k_conv1(const float* __restrict__ spec, const float* __restrict__ w,
                        const float* __restrict__ cb, const float* __restrict__ bg,
                        const float* __restrict__ bbt, const float* __restrict__ bm,
                        const float* __restrict__ bv) {
    __shared__ float sw[C1N*9];
    __shared__ float ssc[C1N], sbi[C1N];
    for (int i = threadIdx.x; i < C1N*9; i += blockDim.x) sw[i] = w[i];
    if (threadIdx.x < C1N) {
        float sc = bg[threadIdx.x] * rsqrtf(bv[threadIdx.x] + BNEPS);
        ssc[threadIdx.x] = sc;
        sbi[threadIdx.x] = (cb[threadIdx.x] - bm[threadIdx.x]) * sc + bbt[threadIdx.x];
    }
    __syncthreads();
    int idx = blockIdx.x * blockDim.x + threadIdx.x;
    if (idx >= BB*TT*FF) return;
    int f = idx % FF;
    int t = (idx / FF) % TT;
    int b = idx / (FF*TT);
    const float* sp = spec + (size_t)b * TT * FF;
    float in[3][3];
    #pragma unroll
    for (int dt = 0; dt < 3; dt++) {
        int tt = t + dt - 1;
        #pragma unroll
        for (int df = 0; df < 3; df++) {
            int ff = f + df - 1;
            in[dt][df] = (tt >= 0 && tt < TT && ff >= 0 && ff < FF) ? sp[tt*FF + ff] : 0.f;
        }
    }
    #pragma unroll
    for (int c = 0; c < C1N; c++) {
        float acc = 0.f;
        #pragma unroll
        for (int k9 = 0; k9 < 9; k9++)
            acc = fmaf(in[k9/3][k9%3], sw[c*9 + k9], acc);
        float val = acc * ssc[c] + sbi[c];
        g_y1[(((size_t)b*C1N + c)*TT + t)*FF + f] = fmaxf(val, 0.f);
    }
}

// ---------------- K2: conv2(5->5) + BN + ReLU + maxpool(W/2)  (R5 scalar) --
__global__ void k_conv2pool(const float* __restrict__ w, const float* __restrict__ cb,
                            const float* __restrict__ bg, const float* __restrict__ bbt,
                            const float* __restrict__ bm, const float* __restrict__ bv) {
    __shared__ float sw[C1N*C1N*9];
    __shared__ float ssc[C1N], sbi[C1N];
    for (int i = threadIdx.x; i < C1N*C1N*9; i += blockDim.x) sw[i] = w[i];
    if (threadIdx.x < C1N) {
        float sc = bg[threadIdx.x] * rsqrtf(bv[threadIdx.x] + BNEPS);
        ssc[threadIdx.x] = sc;
        sbi[threadIdx.x] = (cb[threadIdx.x] - bm[threadIdx.x]) * sc + bbt[threadIdx.x];
    }
    __syncthreads();
    int idx = blockIdx.x * blockDim.x + threadIdx.x;
    if (idx >= BB*TT*F2) return;
    int fp = idx % F2;
    int t = (idx / F2) % TT;
    int b = idx / (F2*TT);
    float acc0[C1N], acc1[C1N];
    #pragma unroll
    for (int c = 0; c < C1N; c++) { acc0[c] = 0.f; acc1[c] = 0.f; }
    #pragma unroll
    for (int ci = 0; ci < C1N; ci++) {
        const float* base = g_y1 + ((size_t)b*C1N + ci)*TT*FF;
        float patch[3][4];
        #pragma unroll
        for (int dt = 0; dt < 3; dt++) {
            int tt = t + dt - 1;
            #pragma unroll
            for (int df = 0; df < 4; df++) {
                int ff = 2*fp + df - 1;
                patch[dt][df] = (tt >= 0 && tt < TT && ff >= 0 && ff < FF) ? base[tt*FF + ff] : 0.f;
            }
        }
        #pragma unroll
        for (int co = 0; co < C1N; co++) {
            const float* wp = &sw[(co*C1N + ci)*9];
            #pragma unroll
            for (int dt = 0; dt < 3; dt++) {
                #pragma unroll
                for (int df = 0; df < 3; df++) {
                    float wv_ = wp[dt*3 + df];
                    acc0[co] = fmaf(patch[dt][df],     wv_, acc0[co]);
                    acc1[co] = fmaf(patch[dt][df + 1], wv_, acc1[co]);
                }
            }
        }
    }
    #pragma unroll
    for (int co = 0; co < C1N; co++) {
        float v0 = fmaxf(acc0[co]*ssc[co] + sbi[co], 0.f);
        float v1 = fmaxf(acc1[co]*ssc[co] + sbi[co], 0.f);
        g_y2[(((size_t)b*C1N + co)*TT + t)*F2 + fp] = fmaxf(v0, v1);
    }
}

// ---------------- K3: conv3(5->11) + BN + ReLU + maxpool + transpose (R5) --
__global__ void k_conv3pool(const float* __restrict__ w, const float* __restrict__ cb,
                            const float* __restrict__ bg, const float* __restrict__ bbt,
                            const float* __restrict__ bm, const float* __restrict__ bv) {
    __shared__ float sw[C2N*C1N*9];   // 495 floats
    __shared__ float ssc[C2N], sbi[C2N];
    for (int i = threadIdx.x; i < C2N*C1N*9; i += blockDim.x) sw[i] = w[i];
    if (threadIdx.x < C2N) {
        float sc = bg[threadIdx.x] * rsqrtf(bv[threadIdx.x] + BNEPS);
        ssc[threadIdx.x] = sc;
        sbi[threadIdx.x] = (cb[threadIdx.x] - bm[threadIdx.x]) * sc + bbt[threadIdx.x];
    }
    __syncthreads();
    int idx = blockIdx.x * blockDim.x + threadIdx.x;
    if (idx >= BB*TT*F3) return;
    int fp = idx % F3;
    int t = (idx / F3) % TT;
    int b = idx / (F3*TT);
    float acc0[C2N], acc1[C2N];
    #pragma unroll
    for (int c = 0; c < C2N; c++) { acc0[c] = 0.f; acc1[c] = 0.f; }
    #pragma unroll
    for (int ci = 0; ci < C1N; ci++) {
        const float* base = g_y2 + ((size_t)b*C1N + ci)*TT*F2;
        float patch[3][4];
        #pragma unroll
        for (int dt = 0; dt < 3; dt++) {
            int tt = t + dt - 1;
            #pragma unroll
            for (int df = 0; df < 4; df++) {
                int ff = 2*fp + df - 1;
                patch[dt][df] = (tt >= 0 && tt < TT && ff >= 0 && ff < F2) ? base[tt*F2 + ff] : 0.f;
            }
        }
        #pragma unroll
        for (int co = 0; co < C2N; co++) {
            const float* wp = &sw[(co*C1N + ci)*9];
            #pragma unroll
            for (int dt = 0; dt < 3; dt++) {
                #pragma unroll
                for (int df = 0; df < 3; df++) {
                    float wv_ = wp[dt*3 + df];
                    acc0[co] = fmaf(patch[dt][df],     wv_, acc0[co]);
                    acc1[co] = fmaf(patch[dt][df + 1], wv_, acc1[co]);
                }
            }
        }
    }
    size_t rowbase = ((size_t)b*TT + t)*FEATP;
    #pragma unroll
    for (int co = 0; co < C2N; co++) {
        float v0 = fmaxf(acc0[co]*ssc[co] + sbi[co], 0.f);
        float v1 = fmaxf(acc1[co]*ssc[co] + sbi[co], 0.f);
        g_x627[rowbase + co*F3 + fp] = fmaxf(v0, v1);
    }
    // zero the 13 pad columns (627..639) of this row
    if (fp < FEATP - FEAT) g_x627[rowbase + FEAT + fp] = 0.f;
}

// ---------------- K4: fused fc+qkv GEMM (20480 x 640p) @ (640p x 144) ------
// 64-row M tiles (320 blocks), 256 threads, 4 rows x 9 cols per thread,
// double-buffered smem, float4 global loads.
__global__ __launch_bounds__(256) void k_fcqkv() {
    __shared__ float sA[2][64][33];
    __shared__ float sW[2][NQKV][33];
    const int m0 = blockIdx.x * 64;
    const int tid = threadIdx.x;
    const int tx = tid % 16;      // cols tx + 16*j, j=0..8
    const int ty = tid / 16;      // 0..15 -> rows 4*ty .. 4*ty+3

    float acc[4][9];
    #pragma unroll
    for (int r = 0; r < 4; r++)
        #pragma unroll
        for (int j = 0; j < 9; j++) acc[r][j] = 0.f;

    float4 pa[2];   // A: 64 rows x 32 k = 512 float4, 2 per thread
    float4 pw[5];   // W: 144 rows x 32 k = 1152 float4, 4.5 per thread

    // ---- preload tile 0 ----
    {
        #pragma unroll
        for (int u = 0; u < 2; u++) {
            int id = tid + 256*u, row = id >> 3, ks = id & 7;
            pa[u] = *(const float4*)(g_x627 + (size_t)(m0 + row)*FEATP + 4*ks);
        }
        #pragma unroll
        for (int u = 0; u < 5; u++) {
            int id = tid + 256*u;
            if (id < 1152) {
                int row = id >> 3, ks = id & 7;
                pw[u] = *(const float4*)(g_w2 + (size_t)row*FEATP + 4*ks);
            }
        }
        #pragma unroll
        for (int u = 0; u < 2; u++) {
            int id = tid + 256*u, row = id >> 3, ks = id & 7;
            sA[0][row][4*ks+0] = pa[u].x; sA[0][row][4*ks+1] = pa[u].y;
            sA[0][row][4*ks+2] = pa[u].z; sA[0][row][4*ks+3] = pa[u].w;
        }
        #pragma unroll
        for (int u = 0; u < 5; u++) {
            int id = tid + 256*u;
            if (id < 1152) {
                int row = id >> 3, ks = id & 7;
                sW[0][row][4*ks+0] = pw[u].x; sW[0][row][4*ks+1] = pw[u].y;
                sW[0][row][4*ks+2] = pw[u].z; sW[0][row][4*ks+3] = pw[u].w;
            }
        }
    }
    __syncthreads();

    const int NIT = FEATP / 32;   // 20
    for (int it = 0; it < NIT; it++) {
        const int buf = it & 1;
        if (it + 1 < NIT) {
            const int k0 = (it + 1) * 32;
            #pragma unroll
            for (int u = 0; u < 2; u++) {
                int id = tid + 256*u, row = id >> 3, ks = id & 7;
                pa[u] = *(const float4*)(g_x627 + (size_t)(m0 + row)*FEATP + k0 + 4*ks);
            }
            #pragma unroll
            for (int u = 0; u < 5; u++) {
                int id = tid + 256*u;
                if (id < 1152) {
                    int row = id >> 3, ks = id & 7;
                    pw[u] = *(const float4*)(g_w2 + (size_t)row*FEATP + k0 + 4*ks);
                }
            }
        }
        #pragma unroll 8
        for (int kk = 0; kk < 32; kk++) {
            float a0 = sA[buf][4*ty+0][kk];
            float a1 = sA[buf][4*ty+1][kk];
            float a2 = sA[buf][4*ty+2][kk];
            float a3 = sA[buf][4*ty+3][kk];
            #pragma unroll
            for (int j = 0; j < 9; j++) {
                float wv_ = sW[buf][tx + 16*j][kk];
                acc[0][j] = fmaf(a0, wv_, acc[0][j]);
                acc[1][j] = fmaf(a1, wv_, acc[1][j]);
                acc[2][j] = fmaf(a2, wv_, acc[2][j]);
                acc[3][j] = fmaf(a3, wv_, acc[3][j]);
            }
        }
        if (it + 1 < NIT) {
            const int nb = buf ^ 1;
            #pragma unroll
            for (int u = 0; u < 2; u++) {
                int id = tid + 256*u, row = id >> 3, ks = id & 7;
                sA[nb][row][4*ks+0] = pa[u].x; sA[nb][row][4*ks+1] = pa[u].y;
                sA[nb][row][4*ks+2] = pa[u].z; sA[nb][row][4*ks+3] = pa[u].w;
            }
            #pragma unroll
            for (int u = 0; u < 5; u++) {
                int id = tid + 256*u;
                if (id < 1152) {
                    int row = id >> 3, ks = id & 7;
                    sW[nb][row][4*ks+0] = pw[u].x; sW[nb][row][4*ks+1] = pw[u].y;
                    sW[nb][row][4*ks+2] = pw[u].z; sW[nb][row][4*ks+3] = pw[u].w;
                }
            }
        }
        __syncthreads();
    }

    #pragma unroll
    for (int j = 0; j < 9; j++) {
        float bj = g_b2[tx + 16*j];
        #pragma unroll
        for (int r = 0; r < 4; r++)
            g_qkv[(size_t)(m0 + 4*ty + r)*NQKV + tx + 16*j] = acc[r][j] + bj;
    }
}

// ---------------- K6: sliding-window attention -----------------------------
#define TTILE 64
__global__ void k_attn(const float* __restrict__ rel, float* __restrict__ a_out) {
    __shared__ float ks[TTILE + 30][49];
    __shared__ float vs[TTILE + 30][49];
    __shared__ float srel[MCN*KW];
    int b  = blockIdx.x / (TT / TTILE);
    int t0 = (blockIdx.x % (TT / TTILE)) * TTILE;

    for (int i = threadIdx.x; i < MCN*KW; i += 256) srel[i] = rel[i];
    for (int i = threadIdx.x; i < (TTILE + 30)*MCN; i += 256) {
        int row = i / MCN, col = i % MCN;
        int t = t0 + row - PADW;
        float kv = 0.f, vv = 0.f;
        if (t >= 0 && t < TT) {
            const float* p = g_qkv + ((size_t)b*TT + t)*NQKV;
            kv = p[48 + col];
            vv = p[96 + col];
        }
        ks[row][col] = kv;
        vs[row][col] = vv;
    }
    __syncthreads();

    for (int item = threadIdx.x; item < TTILE*GN; item += 256) {
        int g  = item % GN;
        int tl = item / GN;
        int t = t0 + tl;
        int gd = g * DH;
        const float* qp = g_qkv + ((size_t)b*TT + t)*NQKV + gd;
        float q0 = qp[0], q1 = qp[1], q2 = qp[2], q3 = qp[3], q4 = qp[4], q5 = qp[5];

        float e[KW];
        float emax = -1e30f;
        #pragma unroll
        for (int kk = 0; kk < KW; kk++) {
            float s;
            s =          q0 * (ks[tl + kk][gd + 0] + srel[(gd + 0)*KW + kk]);
            s = fmaf(q1, (ks[tl + kk][gd + 1] + srel[(gd + 1)*KW + kk]), s);
            s = fmaf(q2, (ks[tl + kk][gd + 2] + srel[(gd + 2)*KW + kk]), s);
            s = fmaf(q3, (ks[tl + kk][gd + 3] + srel[(gd + 3)*KW + kk]), s);
            s = fmaf(q4, (ks[tl + kk][gd + 4] + srel[(gd + 4)*KW + kk]), s);
            s = fmaf(q5, (ks[tl + kk][gd + 5] + srel[(gd + 5)*KW + kk]), s);
            e[kk] = s;
            emax = fmaxf(emax, s);
        }
        float sum = 0.f;
        #pragma unroll
        for (int kk = 0; kk < KW; kk++) {
            e[kk] = __expf(e[kk] - emax);
            sum += e[kk];
        }
        float inv = 1.f / sum;
        float o0 = 0.f, o1 = 0.f, o2 = 0.f, o3 = 0.f, o4 = 0.f, o5 = 0.f;
        float* ap = a_out + (((size_t)b*TT + t)*GN + g)*KW;
        #pragma unroll
        for (int kk = 0; kk < KW; kk++) {
            float p = e[kk] * inv;
            ap[kk] = p;
            o0 = fmaf(p, vs[tl + kk][gd + 0], o0);
            o1 = fmaf(p, vs[tl + kk][gd + 1], o1);
            o2 = fmaf(p, vs[tl + kk][gd + 2], o2);
            o3 = fmaf(p, vs[tl + kk][gd + 3], o3);
            o4 = fmaf(p, vs[tl + kk][gd + 4], o4);
            o5 = fmaf(p, vs[tl + kk][gd + 5], o5);
        }
        float* op = g_out48 + ((size_t)b*TT + t)*MCN + gd;
        op[0] = o0; op[1] = o1; op[2] = o2; op[3] = o3; op[4] = o4; op[5] = o5;
    }
}

// ---------------- K7: LayerNorm(48) + linear(48->88) + sigmoid -------------
__global__ void k_lnout(const float* __restrict__ lng, const float* __restrict__ lnb,
                        const float* __restrict__ lw, const float* __restrict__ lb,
                        float* __restrict__ out) {
    __shared__ float slw[OFN*49];
    __shared__ float sh[8][MCN];
    __shared__ float sg[MCN], sb[MCN], slb[OFN];
    for (int i = threadIdx.x; i < OFN*MCN; i += 256) {
        int n = i / MCN, j = i % MCN;
        slw[n*49 + j] = lw[i];
    }
    if (threadIdx.x < MCN) { sg[threadIdx.x] = lng[threadIdx.x]; sb[threadIdx.x] = lnb[threadIdx.x]; }
    if (threadIdx.x < OFN) slb[threadIdx.x] = lb[threadIdx.x];
    __syncthreads();

    int warp = threadIdx.x / 32, lane = threadIdx.x % 32;
    int row = blockIdx.x * 8 + warp;
    const float* xp = g_out48 + (size_t)row*MCN;
    float x0 = xp[lane];
    float x1 = (lane < 16) ? xp[lane + 32] : 0.f;
    float s  = x0 + x1;
    float s2 = x0*x0 + x1*x1;
    #pragma unroll
    for (int off = 16; off > 0; off >>= 1) {
        s  += __shfl_xor_sync(0xFFFFFFFFu, s,  off);
        s2 += __shfl_xor_sync(0xFFFFFFFFu, s2, off);
    }
    float mu = s * (1.f/48.f);
    float var = s2 * (1.f/48.f) - mu*mu;
    float rstd = rsqrtf(var + 1e-5f);
    sh[warp][lane] = (x0 - mu) * rstd * sg[lane] + sb[lane];
    if (lane < 16) sh[warp][lane + 32] = (x1 - mu) * rstd * sg[lane + 32] + sb[lane + 32];
    __syncwarp();

    #pragma unroll
    for (int jj = 0; jj < 3; jj++) {
        int n = lane + 32*jj;
        if (n < OFN) {
            float z = slb[n];
            #pragma unroll
            for (int j = 0; j < MCN; j++)
                z = fmaf(sh[warp][j], slw[n*49 + j], z);
            out[(size_t)row*OFN + n] = 1.f / (1.f + __expf(-z));
        }
    }
}

// ---------------- launch ---------------------------------------------------
extern "C" void kernel_launch(void* const* d_in, const int* in_sizes, int n_in,
                              void* d_out, int out_size) {
    const float* spec  = (const float*)d_in[0];
    const float* c1_w  = (const float*)d_in[1];
    const float* c1_b  = (const float*)d_in[2];
    const float* bn1_g = (const float*)d_in[3];
    const float* bn1_b = (const float*)d_in[4];
    const float* bn1_m = (const float*)d_in[5];
    const float* bn1_v = (const float*)d_in[6];
    const float* c2_w  = (const float*)d_in[7];
    const float* c2_b  = (const float*)d_in[8];
    const float* bn2_g = (const float*)d_in[9];
    const float* bn2_b = (const float*)d_in[10];
    const float* bn2_m = (const float*)d_in[11];
    const float* bn2_v = (const float*)d_in[12];
    const float* c3_w  = (const float*)d_in[13];
    const float* c3_b  = (const float*)d_in[14];
    const float* bn3_g = (const float*)d_in[15];
    const float* bn3_b = (const float*)d_in[16];
    const float* bn3_m = (const float*)d_in[17];
    const float* bn3_v = (const float*)d_in[18];
    const float* fc_w  = (const float*)d_in[19];
    const float* fc_b  = (const float*)d_in[20];
    const float* wq    = (const float*)d_in[21];
    const float* wk    = (const float*)d_in[22];
    const float* wv    = (const float*)d_in[23];
    const float* rel   = (const float*)d_in[24];
    const float* ln_g  = (const float*)d_in[25];
    const float* ln_b  = (const float*)d_in[26];
    const float* lin_w = (const float*)d_in[27];
    const float* lin_b = (const float*)d_in[28];

    float* out   = (float*)d_out;                 // frame_pred (B,T,88)
    float* a_out = out + FRAME_ELEMS;             // a (B,T,8,31)

    k_prep_w2<<<NQKV/16, 256>>>(wq, wk, wv, fc_w, fc_b);
    int n1 = BB*TT*FF;
    k_conv1<<<(n1 + 255)/256, 256>>>(spec, c1_w, c1_b, bn1_g, bn1_b, bn1_m, bn1_v);
    int n2 = BB*TT*F2;
    k_conv2pool<<<(n2 + 255)/256, 256>>>(c2_w, c2_b, bn2_g, bn2_b, bn2_m, bn2_v);
    int n3 = BB*TT*F3;
    k_conv3pool<<<(n3 + 255)/256, 256>>>(c3_w, c3_b, bn3_g, bn3_b, bn3_m, bn3_v);
    k_fcqkv<<<(BB*TT)/64, 256>>>();
    k_attn<<<BB*(TT/TTILE), 256>>>(rel, a_out);
    k_lnout<<<(BB*TT)/8, 256>>>(ln_g, ln_b, lin_w, lin_b, out);
}

// round 9
// speedup vs baseline: 1.0877x; 1.0877x over previous
#include <cuda_runtime.h>

#define BB 8
#define TT 2560
#define FF 229
#define C1N 5
#define C2N 11
#define F2 114
#define F3 57
#define FEAT 627       // C2N * F3
#define FEATP 640      // padded K (float4-aligned)
#define OFN 88
#define NQKV 144
#define MCN 48
#define GN 8
#define DH 6
#define KW 31
#define PADW 15
#define BNEPS 1e-5f
#define FRAME_ELEMS (BB*TT*OFN)

// ---------------- scratch (device globals; no allocation allowed) ----------
__device__ float g_y1[(size_t)BB*C1N*TT*FF];     // conv1 out  (B,C1,T,F)
__device__ float g_y2[(size_t)BB*C1N*TT*F2];     // conv2+pool (B,C1,T,F2)
__device__ float g_x627[(size_t)BB*TT*FEATP];    // conv3+pool, (B*T, 640) padded
__device__ float g_w2[(size_t)NQKV*FEATP];       // folded W2 = Wqkv @ fc_w  (144, 640)
__device__ float g_b2[NQKV];                     // folded bias = Wqkv @ fc_b
__device__ float g_qkv[(size_t)BB*TT*NQKV];      // q|k|v (B*T, 144)
__device__ float g_out48[(size_t)BB*TT*MCN];     // attention out (B*T, 48)

// ---------------- K0: fold fc into qkv:  W2[n,k] = sum_j Wqkv[n,j]*fc_w[j,k]
// grid (10 col-groups x 9 row-groups), 64 threads; one k-column per thread.
__global__ void k_prep_w2(const float* __restrict__ wq, const float* __restrict__ wk,
                          const float* __restrict__ wv, const float* __restrict__ fcw,
                          const float* __restrict__ fcb) {
    __shared__ float sq[16*OFN];
    int n0 = blockIdx.y * 16;
    int k  = blockIdx.x * 64 + threadIdx.x;
    for (int i = threadIdx.x; i < 16*OFN; i += 64) {
        int n = n0 + i / OFN, j = i % OFN;
        const float* src = (n < 48) ? (wq + n*OFN) : (n < 96) ? (wk + (n-48)*OFN)
                                                              : (wv + (n-96)*OFN);
        sq[i] = src[j];
    }
    __syncthreads();
    if (blockIdx.x == 0 && threadIdx.x < 16) {
        float s = 0.f;
        for (int j = 0; j < OFN; j++) s += sq[threadIdx.x*OFN + j] * fcb[j];
        g_b2[n0 + threadIdx.x] = s;
    }
    float acc[16];
    #pragma unroll
    for (int i = 0; i < 16; i++) acc[i] = 0.f;
    if (k < FEAT) {
        for (int j = 0; j < OFN; j++) {
            float f = fcw[j*FEAT + k];
            #pragma unroll
            for (int i = 0; i < 16; i++) acc[i] = fmaf(sq[i*OFN + j], f, acc[i]);
        }
    }
    #pragma unroll
    for (int i = 0; i < 16; i++) g_w2[(size_t)(n0 + i)*FEATP + k] = acc[i];
}

// ---------------- K1: conv1(1->5) + BN + ReLU ------------------------------
__global__ void k_conv1(const float* __restrict__ spec, const float* __restrict__ w,
                        const float* __restrict__ cb, const float* __restrict__ bg,
                        const float* __restrict__ bbt, const float* __restrict__ bm,
                        const float* __restrict__ bv) {
    __shared__ float sw[C1N*9];
    __shared__ float ssc[C1N], sbi[C1N];
    for (int i = threadIdx.x; i < C1N*9; i += blockDim.x) sw[i] = w[i];
    if (threadIdx.x < C1N) {
        float sc = bg[threadIdx.x] * rsqrtf(bv[threadIdx.x] + BNEPS);
        ssc[threadIdx.x] = sc;
        sbi[threadIdx.x] = (cb[threadIdx.x] - bm[threadIdx.x]) * sc + bbt[threadIdx.x];
    }
    __syncthreads();
    int idx = blockIdx.x * blockDim.x + threadIdx.x;
    if (idx >= BB*TT*FF) return;
    int f = idx % FF;
    int t = (idx / FF) % TT;
    int b = idx / (FF*TT);
    const float* sp = spec + (size_t)b * TT * FF;
    float in[3][3];
    #pragma unroll
    for (int dt = 0; dt < 3; dt++) {
        int tt = t + dt - 1;
        #pragma unroll
        for (int df = 0; df < 3; df++) {
            int ff = f + df - 1;
            in[dt][df] = (tt >= 0 && tt < TT && ff >= 0 && ff < FF) ? sp[tt*FF + ff] : 0.f;
        }
    }
    #pragma unroll
    for (int c = 0; c < C1N; c++) {
        float acc = 0.f;
        #pragma unroll
        for (int k9 = 0; k9 < 9; k9++)
            acc = fmaf(in[k9/3][k9%3], sw[c*9 + k9], acc);
        float val = acc * ssc[c] + sbi[c];
        g_y1[(((size_t)b*C1N + c)*TT + t)*FF + f] = fmaxf(val, 0.f);
    }
}

// ---------------- K2: conv2(5->5) + BN + ReLU + maxpool(W/2)  (R5 scalar) --
__global__ void k_conv2pool(const float* __restrict__ w, const float* __restrict__ cb,
                            const float* __restrict__ bg, const float* __restrict__ bbt,
                            const float* __restrict__ bm, const float* __restrict__ bv) {
    __shared__ float sw[C1N*C1N*9];
    __shared__ float ssc[C1N], sbi[C1N];
    for (int i = threadIdx.x; i < C1N*C1N*9; i += blockDim.x) sw[i] = w[i];
    if (threadIdx.x < C1N) {
        float sc = bg[threadIdx.x] * rsqrtf(bv[threadIdx.x] + BNEPS);
        ssc[threadIdx.x] = sc;
        sbi[threadIdx.x] = (cb[threadIdx.x] - bm[threadIdx.x]) * sc + bbt[threadIdx.x];
    }
    __syncthreads();
    int idx = blockIdx.x * blockDim.x + threadIdx.x;
    if (idx >= BB*TT*F2) return;
    int fp = idx % F2;
    int t = (idx / F2) % TT;
    int b = idx / (F2*TT);
    float acc0[C1N], acc1[C1N];
    #pragma unroll
    for (int c = 0; c < C1N; c++) { acc0[c] = 0.f; acc1[c] = 0.f; }
    #pragma unroll
    for (int ci = 0; ci < C1N; ci++) {
        const float* base = g_y1 + ((size_t)b*C1N + ci)*TT*FF;
        float patch[3][4];
        #pragma unroll
        for (int dt = 0; dt < 3; dt++) {
            int tt = t + dt - 1;
            #pragma unroll
            for (int df = 0; df < 4; df++) {
                int ff = 2*fp + df - 1;
                patch[dt][df] = (tt >= 0 && tt < TT && ff >= 0 && ff < FF) ? base[tt*FF + ff] : 0.f;
            }
        }
        #pragma unroll
        for (int co = 0; co < C1N; co++) {
            const float* wp = &sw[(co*C1N + ci)*9];
            #pragma unroll
            for (int dt = 0; dt < 3; dt++) {
                #pragma unroll
                for (int df = 0; df < 3; df++) {
                    float wv_ = wp[dt*3 + df];
                    acc0[co] = fmaf(patch[dt][df],     wv_, acc0[co]);
                    acc1[co] = fmaf(patch[dt][df + 1], wv_, acc1[co]);
                }
            }
        }
    }
    #pragma unroll
    for (int co = 0; co < C1N; co++) {
        float v0 = fmaxf(acc0[co]*ssc[co] + sbi[co], 0.f);
        float v1 = fmaxf(acc1[co]*ssc[co] + sbi[co], 0.f);
        g_y2[(((size_t)b*C1N + co)*TT + t)*F2 + fp] = fmaxf(v0, v1);
    }
}

// ---------------- K3: conv3(5->11) + BN + ReLU + maxpool + transpose (R5) --
__global__ void k_conv3pool(const float* __restrict__ w, const float* __restrict__ cb,
                            const float* __restrict__ bg, const float* __restrict__ bbt,
                            const float* __restrict__ bm, const float* __restrict__ bv) {
    __shared__ float sw[C2N*C1N*9];   // 495 floats
    __shared__ float ssc[C2N], sbi[C2N];
    for (int i = threadIdx.x; i < C2N*C1N*9; i += blockDim.x) sw[i] = w[i];
    if (threadIdx.x < C2N) {
        float sc = bg[threadIdx.x] * rsqrtf(bv[threadIdx.x] + BNEPS);
        ssc[threadIdx.x] = sc;
        sbi[threadIdx.x] = (cb[threadIdx.x] - bm[threadIdx.x]) * sc + bbt[threadIdx.x];
    }
    __syncthreads();
    int idx = blockIdx.x * blockDim.x + threadIdx.x;
    if (idx >= BB*TT*F3) return;
    int fp = idx % F3;
    int t = (idx / F3) % TT;
    int b = idx / (F3*TT);
    float acc0[C2N], acc1[C2N];
    #pragma unroll
    for (int c = 0; c < C2N; c++) { acc0[c] = 0.f; acc1[c] = 0.f; }
    #pragma unroll
    for (int ci = 0; ci < C1N; ci++) {
        const float* base = g_y2 + ((size_t)b*C1N + ci)*TT*F2;
        float patch[3][4];
        #pragma unroll
        for (int dt = 0; dt < 3; dt++) {
            int tt = t + dt - 1;
            #pragma unroll
            for (int df = 0; df < 4; df++) {
                int ff = 2*fp + df - 1;
                patch[dt][df] = (tt >= 0 && tt < TT && ff >= 0 && ff < F2) ? base[tt*F2 + ff] : 0.f;
            }
        }
        #pragma unroll
        for (int co = 0; co < C2N; co++) {
            const float* wp = &sw[(co*C1N + ci)*9];
            #pragma unroll
            for (int dt = 0; dt < 3; dt++) {
                #pragma unroll
                for (int df = 0; df < 3; df++) {
                    float wv_ = wp[dt*3 + df];
                    acc0[co] = fmaf(patch[dt][df],     wv_, acc0[co]);
                    acc1[co] = fmaf(patch[dt][df + 1], wv_, acc1[co]);
                }
            }
        }
    }
    size_t rowbase = ((size_t)b*TT + t)*FEATP;
    #pragma unroll
    for (int co = 0; co < C2N; co++) {
        float v0 = fmaxf(acc0[co]*ssc[co] + sbi[co], 0.f);
        float v1 = fmaxf(acc1[co]*ssc[co] + sbi[co], 0.f);
        g_x627[rowbase + co*F3 + fp] = fmaxf(v0, v1);
    }
    // zero the 13 pad columns (627..639) of this row
    if (fp < FEATP - FEAT) g_x627[rowbase + FEAT + fp] = 0.f;
}

// ---------------- K4: fused fc+qkv GEMM (20480 x 640p) @ (640p x 144) ------
// 64-row M tiles (320 blocks), 256 threads, 4 rows x 9 cols per thread,
// double-buffered smem, float4 global loads.
__global__ __launch_bounds__(256) void k_fcqkv() {
    __shared__ float sA[2][64][33];
    __shared__ float sW[2][NQKV][33];
    const int m0 = blockIdx.x * 64;
    const int tid = threadIdx.x;
    const int tx = tid % 16;      // cols tx + 16*j, j=0..8
    const int ty = tid / 16;      // 0..15 -> rows 4*ty .. 4*ty+3

    float acc[4][9];
    #pragma unroll
    for (int r = 0; r < 4; r++)
        #pragma unroll
        for (int j = 0; j < 9; j++) acc[r][j] = 0.f;

    float4 pa[2];   // A: 64 rows x 32 k = 512 float4, 2 per thread
    float4 pw[5];   // W: 144 rows x 32 k = 1152 float4, 4.5 per thread

    // ---- preload tile 0 ----
    {
        #pragma unroll
        for (int u = 0; u < 2; u++) {
            int id = tid + 256*u, row = id >> 3, ks = id & 7;
            pa[u] = *(const float4*)(g_x627 + (size_t)(m0 + row)*FEATP + 4*ks);
        }
        #pragma unroll
        for (int u = 0; u < 5; u++) {
            int id = tid + 256*u;
            if (id < 1152) {
                int row = id >> 3, ks = id & 7;
                pw[u] = *(const float4*)(g_w2 + (size_t)row*FEATP + 4*ks);
            }
        }
        #pragma unroll
        for (int u = 0; u < 2; u++) {
            int id = tid + 256*u, row = id >> 3, ks = id & 7;
            sA[0][row][4*ks+0] = pa[u].x; sA[0][row][4*ks+1] = pa[u].y;
            sA[0][row][4*ks+2] = pa[u].z; sA[0][row][4*ks+3] = pa[u].w;
        }
        #pragma unroll
        for (int u = 0; u < 5; u++) {
            int id = tid + 256*u;
            if (id < 1152) {
                int row = id >> 3, ks = id & 7;
                sW[0][row][4*ks+0] = pw[u].x; sW[0][row][4*ks+1] = pw[u].y;
                sW[0][row][4*ks+2] = pw[u].z; sW[0][row][4*ks+3] = pw[u].w;
            }
        }
    }
    __syncthreads();

    const int NIT = FEATP / 32;   // 20
    for (int it = 0; it < NIT; it++) {
        const int buf = it & 1;
        if (it + 1 < NIT) {
            const int k0 = (it + 1) * 32;
            #pragma unroll
            for (int u = 0; u < 2; u++) {
                int id = tid + 256*u, row = id >> 3, ks = id & 7;
                pa[u] = *(const float4*)(g_x627 + (size_t)(m0 + row)*FEATP + k0 + 4*ks);
            }
            #pragma unroll
            for (int u = 0; u < 5; u++) {
                int id = tid + 256*u;
                if (id < 1152) {
                    int row = id >> 3, ks = id & 7;
                    pw[u] = *(const float4*)(g_w2 + (size_t)row*FEATP + k0 + 4*ks);
                }
            }
        }
        #pragma unroll 8
        for (int kk = 0; kk < 32; kk++) {
            float a0 = sA[buf][4*ty+0][kk];
            float a1 = sA[buf][4*ty+1][kk];
            float a2 = sA[buf][4*ty+2][kk];
            float a3 = sA[buf][4*ty+3][kk];
            #pragma unroll
            for (int j = 0; j < 9; j++) {
                float wv_ = sW[buf][tx + 16*j][kk];
                acc[0][j] = fmaf(a0, wv_, acc[0][j]);
                acc[1][j] = fmaf(a1, wv_, acc[1][j]);
                acc[2][j] = fmaf(a2, wv_, acc[2][j]);
                acc[3][j] = fmaf(a3, wv_, acc[3][j]);
            }
        }
        if (it + 1 < NIT) {
            const int nb = buf ^ 1;
            #pragma unroll
            for (int u = 0; u < 2; u++) {
                int id = tid + 256*u, row = id >> 3, ks = id & 7;
                sA[nb][row][4*ks+0] = pa[u].x; sA[nb][row][4*ks+1] = pa[u].y;
                sA[nb][row][4*ks+2] = pa[u].z; sA[nb][row][4*ks+3] = pa[u].w;
            }
            #pragma unroll
            for (int u = 0; u < 5; u++) {
                int id = tid + 256*u;
                if (id < 1152) {
                    int row = id >> 3, ks = id & 7;
                    sW[nb][row][4*ks+0] = pw[u].x; sW[nb][row][4*ks+1] = pw[u].y;
                    sW[nb][row][4*ks+2] = pw[u].z; sW[nb][row][4*ks+3] = pw[u].w;
                }
            }
        }
        __syncthreads();
    }

    #pragma unroll
    for (int j = 0; j < 9; j++) {
        float bj = g_b2[tx + 16*j];
        #pragma unroll
        for (int r = 0; r < 4; r++)
            g_qkv[(size_t)(m0 + 4*ty + r)*NQKV + tx + 16*j] = acc[r][j] + bj;
    }
}

// ---------------- K6: sliding-window attention -----------------------------
#define TTILE 64
__global__ void k_attn(const float* __restrict__ rel, float* __restrict__ a_out) {
    __shared__ float ks[TTILE + 30][49];
    __shared__ float vs[TTILE + 30][49];
    __shared__ float srel[MCN*KW];
    int b  = blockIdx.x / (TT / TTILE);
    int t0 = (blockIdx.x % (TT / TTILE)) * TTILE;

    for (int i = threadIdx.x; i < MCN*KW; i += 256) srel[i] = rel[i];
    for (int i = threadIdx.x; i < (TTILE + 30)*MCN; i += 256) {
        int row = i / MCN, col = i % MCN;
        int t = t0 + row - PADW;
        float kv = 0.f, vv = 0.f;
        if (t >= 0 && t < TT) {
            const float* p = g_qkv + ((size_t)b*TT + t)*NQKV;
            kv = p[48 + col];
            vv = p[96 + col];
        }
        ks[row][col] = kv;
        vs[row][col] = vv;
    }
    __syncthreads();

    for (int item = threadIdx.x; item < TTILE*GN; item += 256) {
        int g  = item % GN;
        int tl = item / GN;
        int t = t0 + tl;
        int gd = g * DH;
        const float* qp = g_qkv + ((size_t)b*TT + t)*NQKV + gd;
        float q0 = qp[0], q1 = qp[1], q2 = qp[2], q3 = qp[3], q4 = qp[4], q5 = qp[5];

        float e[KW];
        float emax = -1e30f;
        #pragma unroll
        for (int kk = 0; kk < KW; kk++) {
            float s;
            s =          q0 * (ks[tl + kk][gd + 0] + srel[(gd + 0)*KW + kk]);
            s = fmaf(q1, (ks[tl + kk][gd + 1] + srel[(gd + 1)*KW + kk]), s);
            s = fmaf(q2, (ks[tl + kk][gd + 2] + srel[(gd + 2)*KW + kk]), s);
            s = fmaf(q3, (ks[tl + kk][gd + 3] + srel[(gd + 3)*KW + kk]), s);
            s = fmaf(q4, (ks[tl + kk][gd + 4] + srel[(gd + 4)*KW + kk]), s);
            s = fmaf(q5, (ks[tl + kk][gd + 5] + srel[(gd + 5)*KW + kk]), s);
            e[kk] = s;
            emax = fmaxf(emax, s);
        }
        float sum = 0.f;
        #pragma unroll
        for (int kk = 0; kk < KW; kk++) {
            e[kk] = __expf(e[kk] - emax);
            sum += e[kk];
        }
        float inv = 1.f / sum;
        float o0 = 0.f, o1 = 0.f, o2 = 0.f, o3 = 0.f, o4 = 0.f, o5 = 0.f;
        float* ap = a_out + (((size_t)b*TT + t)*GN + g)*KW;
        #pragma unroll
        for (int kk = 0; kk < KW; kk++) {
            float p = e[kk] * inv;
            ap[kk] = p;
            o0 = fmaf(p, vs[tl + kk][gd + 0], o0);
            o1 = fmaf(p, vs[tl + kk][gd + 1], o1);
            o2 = fmaf(p, vs[tl + kk][gd + 2], o2);
            o3 = fmaf(p, vs[tl + kk][gd + 3], o3);
            o4 = fmaf(p, vs[tl + kk][gd + 4], o4);
            o5 = fmaf(p, vs[tl + kk][gd + 5], o5);
        }
        float* op = g_out48 + ((size_t)b*TT + t)*MCN + gd;
        op[0] = o0; op[1] = o1; op[2] = o2; op[3] = o3; op[4] = o4; op[5] = o5;
    }
}

// ---------------- K7: LayerNorm(48) + linear(48->88) + sigmoid -------------
__global__ void k_lnout(const float* __restrict__ lng, const float* __restrict__ lnb,
                        const float* __restrict__ lw, const float* __restrict__ lb,
                        float* __restrict__ out) {
    __shared__ float slw[OFN*49];
    __shared__ float sh[8][MCN];
    __shared__ float sg[MCN], sb[MCN], slb[OFN];
    for (int i = threadIdx.x; i < OFN*MCN; i += 256) {
        int n = i / MCN, j = i % MCN;
        slw[n*49 + j] = lw[i];
    }
    if (threadIdx.x < MCN) { sg[threadIdx.x] = lng[threadIdx.x]; sb[threadIdx.x] = lnb[threadIdx.x]; }
    if (threadIdx.x < OFN) slb[threadIdx.x] = lb[threadIdx.x];
    __syncthreads();

    int warp = threadIdx.x / 32, lane = threadIdx.x % 32;
    int row = blockIdx.x * 8 + warp;
    const float* xp = g_out48 + (size_t)row*MCN;
    float x0 = xp[lane];
    float x1 = (lane < 16) ? xp[lane + 32] : 0.f;
    float s  = x0 + x1;
    float s2 = x0*x0 + x1*x1;
    #pragma unroll
    for (int off = 16; off > 0; off >>= 1) {
        s  += __shfl_xor_sync(0xFFFFFFFFu, s,  off);
        s2 += __shfl_xor_sync(0xFFFFFFFFu, s2, off);
    }
    float mu = s * (1.f/48.f);
    float var = s2 * (1.f/48.f) - mu*mu;
    float rstd = rsqrtf(var + 1e-5f);
    sh[warp][lane] = (x0 - mu) * rstd * sg[lane] + sb[lane];
    if (lane < 16) sh[warp][lane + 32] = (x1 - mu) * rstd * sg[lane + 32] + sb[lane + 32];
    __syncwarp();

    #pragma unroll
    for (int jj = 0; jj < 3; jj++) {
        int n = lane + 32*jj;
        if (n < OFN) {
            float z = slb[n];
            #pragma unroll
            for (int j = 0; j < MCN; j++)
                z = fmaf(sh[warp][j], slw[n*49 + j], z);
            out[(size_t)row*OFN + n] = 1.f / (1.f + __expf(-z));
        }
    }
}

// ---------------- launch ---------------------------------------------------
extern "C" void kernel_launch(void* const* d_in, const int* in_sizes, int n_in,
                              void* d_out, int out_size) {
    const float* spec  = (const float*)d_in[0];
    const float* c1_w  = (const float*)d_in[1];
    const float* c1_b  = (const float*)d_in[2];
    const float* bn1_g = (const float*)d_in[3];
    const float* bn1_b = (const float*)d_in[4];
    const float* bn1_m = (const float*)d_in[5];
    const float* bn1_v = (const float*)d_in[6];
    const float* c2_w  = (const float*)d_in[7];
    const float* c2_b  = (const float*)d_in[8];
    const float* bn2_g = (const float*)d_in[9];
    const float* bn2_b = (const float*)d_in[10];
    const float* bn2_m = (const float*)d_in[11];
    const float* bn2_v = (const float*)d_in[12];
    const float* c3_w  = (const float*)d_in[13];
    const float* c3_b  = (const float*)d_in[14];
    const float* bn3_g = (const float*)d_in[15];
    const float* bn3_b = (const float*)d_in[16];
    const float* bn3_m = (const float*)d_in[17];
    const float* bn3_v = (const float*)d_in[18];
    const float* fc_w  = (const float*)d_in[19];
    const float* fc_b  = (const float*)d_in[20];
    const float* wq    = (const float*)d_in[21];
    const float* wk    = (const float*)d_in[22];
    const float* wv    = (const float*)d_in[23];
    const float* rel   = (const float*)d_in[24];
    const float* ln_g  = (const float*)d_in[25];
    const float* ln_b  = (const float*)d_in[26];
    const float* lin_w = (const float*)d_in[27];
    const float* lin_b = (const float*)d_in[28];

    float* out   = (float*)d_out;                 // frame_pred (B,T,88)
    float* a_out = out + FRAME_ELEMS;             // a (B,T,8,31)

    dim3 pgrid(FEATP/64, NQKV/16);
    k_prep_w2<<<pgrid, 64>>>(wq, wk, wv, fc_w, fc_b);
    int n1 = BB*TT*FF;
    k_conv1<<<(n1 + 255)/256, 256>>>(spec, c1_w, c1_b, bn1_g, bn1_b, bn1_m, bn1_v);
    int n2 = BB*TT*F2;
    k_conv2pool<<<(n2 + 255)/256, 256>>>(c2_w, c2_b, bn2_g, bn2_b, bn2_m, bn2_v);
    int n3 = BB*TT*F3;
    k_conv3pool<<<(n3 + 255)/256, 256>>>(c3_w, c3_b, bn3_g, bn3_b, bn3_m, bn3_v);
    k_fcqkv<<<(BB*TT)/64, 256>>>();
    k_attn<<<BB*(TT/TTILE), 256>>>(rel, a_out);
    k_lnout<<<(BB*TT)/8, 256>>>(ln_g, ln_b, lin_w, lin_b, out);
}

// round 11
// speedup vs baseline: 1.1088x; 1.0194x over previous
#include <cuda_runtime.h>

#define BB 8
#define TT 2560
#define FF 229
#define C1N 5
#define C2N 11
#define F2 114
#define F3 57
#define FEAT 627       // C2N * F3
#define FEATP 640      // padded K for fc (float4-aligned)
#define OFN 88
#define MCN 48
#define GN 8
#define DH 6
#define KW 31
#define PADW 15
#define BNEPS 1e-5f
#define FRAME_ELEMS (BB*TT*OFN)

// conv12 tiling
#define TTC 8                 // t-tile
#define SW 232                // padded smem width (f index + 1, zeros at 0 and 230+)
#define SROWS 12              // spec rows t0-2 .. t0+9
#define YROWS 10              // y1 rows   t0-1 .. t0+8
#define SMEM12_FLOATS (SROWS*SW + YROWS*C1N*SW)   // 2784 + 11600 = 14384
#define SMEM12_BYTES  (SMEM12_FLOATS*4)           // 57536

// ---------------- scratch (device globals; no allocation allowed) ----------
__device__ float g_y2[(size_t)BB*C1N*TT*F2];     // conv2+pool (B,C1,T,F2)
__device__ float g_x627[(size_t)BB*TT*FEATP];    // conv3+pool, (B*T, 640) padded
__device__ float g_wfc[(size_t)OFN*FEATP];       // repacked fc_w (88, 640) padded
__device__ float g_x88[(size_t)BB*TT*OFN];       // fc out (B*T, 88)
__device__ float g_qkv[(size_t)BB*TT*144];       // q|k|v (B*T, 144)
__device__ float g_out48[(size_t)BB*TT*MCN];     // attention out (B*T, 48)

// ---------------- K0: repack fc weights into padded layout -----------------
__global__ void k_repack_w(const float* __restrict__ fw) {
    int idx = blockIdx.x * blockDim.x + threadIdx.x;
    if (idx >= OFN*FEATP) return;
    int n = idx / FEATP, k = idx % FEATP;
    g_wfc[idx] = (k < FEAT) ? fw[n*FEAT + k] : 0.f;
}

// ---------------- K1+2 fused: conv1 + BN + ReLU -> (smem) -> conv2 + BN
//                  + ReLU + maxpool(W/2) -> g_y2
__global__ __launch_bounds__(256) void k_conv12(
        const float* __restrict__ spec,
        const float* __restrict__ w1, const float* __restrict__ cb1,
        const float* __restrict__ bg1, const float* __restrict__ bbt1,
        const float* __restrict__ bm1, const float* __restrict__ bv1,
        const float* __restrict__ w2, const float* __restrict__ cb2,
        const float* __restrict__ bg2, const float* __restrict__ bbt2,
        const float* __restrict__ bm2, const float* __restrict__ bv2) {
    extern __shared__ float smem[];
    float* s_spec = smem;                 // [SROWS][SW]
    float* s_y1   = smem + SROWS*SW;      // [YROWS][C1N][SW]

    __shared__ float sw1[C1N*9], sw2[C1N*C1N*9];
    __shared__ float ssc1[C1N], sbi1[C1N], ssc2[C1N], sbi2[C1N];

    const int tid = threadIdx.x;
    const int b  = blockIdx.x / (TT/TTC);
    const int t0 = (blockIdx.x % (TT/TTC)) * TTC;

    for (int i = tid; i < C1N*9; i += 256) sw1[i] = w1[i];
    for (int i = tid; i < C1N*C1N*9; i += 256) sw2[i] = w2[i];
    if (tid < C1N) {
        float sc1 = bg1[tid] * rsqrtf(bv1[tid] + BNEPS);
        ssc1[tid] = sc1;
        sbi1[tid] = (cb1[tid] - bm1[tid]) * sc1 + bbt1[tid];
        float sc2 = bg2[tid] * rsqrtf(bv2[tid] + BNEPS);
        ssc2[tid] = sc2;
        sbi2[tid] = (cb2[tid] - bm2[tid]) * sc2 + bbt2[tid];
    }

    // ---- Phase A: stage spec rows t0-2 .. t0+9, f-shifted by +1, zero pad
    const float* sp = spec + (size_t)b * TT * FF;
    for (int i = tid; i < SROWS*SW; i += 256) {
        int r = i / SW, fo = i % SW;
        int tt = t0 - 2 + r, f = fo - 1;
        float v = (tt >= 0 && tt < TT && f >= 0 && f < FF) ? sp[tt*FF + f] : 0.f;
        s_spec[i] = v;
    }
    __syncthreads();

    // ---- Phase B: conv1+BN+ReLU into s_y1 (zeros for out-of-range t rows)
    // zero the f-pad columns (fo = 0, 230, 231)
    for (int i = tid; i < YROWS*C1N; i += 256) {
        s_y1[i*SW + 0]   = 0.f;
        s_y1[i*SW + 230] = 0.f;
        s_y1[i*SW + 231] = 0.f;
    }
    for (int i = tid; i < YROWS*FF; i += 256) {
        int yr = i / FF, f = i % FF;
        int tt = t0 - 1 + yr;
        float v0 = 0.f, v1 = 0.f, v2 = 0.f, v3 = 0.f, v4 = 0.f;
        if (tt >= 0 && tt < TT) {
            // spec patch: rows yr..yr+2 (sr = yr+dt), cols f..f+2 (stored idx)
            float p[9];
            #pragma unroll
            for (int dt = 0; dt < 3; dt++)
                #pragma unroll
                for (int df = 0; df < 3; df++)
                    p[dt*3 + df] = s_spec[(yr + dt)*SW + f + df];
            float a[C1N];
            #pragma unroll
            for (int c = 0; c < C1N; c++) {
                float acc = 0.f;
                #pragma unroll
                for (int k9 = 0; k9 < 9; k9++)
                    acc = fmaf(p[k9], sw1[c*9 + k9], acc);
                a[c] = fmaxf(acc*ssc1[c] + sbi1[c], 0.f);
            }
            v0 = a[0]; v1 = a[1]; v2 = a[2]; v3 = a[3]; v4 = a[4];
        }
        int base = (yr*C1N)*SW + f + 1;
        s_y1[base + 0*SW] = v0;
        s_y1[base + 1*SW] = v1;
        s_y1[base + 2*SW] = v2;
        s_y1[base + 3*SW] = v3;
        s_y1[base + 4*SW] = v4;
    }
    __syncthreads();

    // ---- Phase C: conv2+BN+ReLU+pool from s_y1 -> g_y2
    for (int i = tid; i < TTC*F2; i += 256) {
        int lt = i / F2, fp = i % F2;
        int t = t0 + lt;
        float acc0[C1N], acc1[C1N];
        #pragma unroll
        for (int c = 0; c < C1N; c++) { acc0[c] = 0.f; acc1[c] = 0.f; }
        #pragma unroll
        for (int ci = 0; ci < C1N; ci++) {
            float patch[3][4];
            #pragma unroll
            for (int dt = 0; dt < 3; dt++) {
                const float* rowp = &s_y1[((lt + dt)*C1N + ci)*SW + 2*fp];
                #pragma unroll
                for (int df = 0; df < 4; df++)
                    patch[dt][df] = rowp[df];   // fo = 2fp+df == ff+1, ff = 2fp+df-1
            }
            #pragma unroll
            for (int co = 0; co < C1N; co++) {
                const float* wp = &sw2[(co*C1N + ci)*9];
                #pragma unroll
                for (int dt = 0; dt < 3; dt++) {
                    #pragma unroll
                    for (int df = 0; df < 3; df++) {
                        float wv_ = wp[dt*3 + df];
                        acc0[co] = fmaf(patch[dt][df],     wv_, acc0[co]);
                        acc1[co] = fmaf(patch[dt][df + 1], wv_, acc1[co]);
                    }
                }
            }
        }
        #pragma unroll
        for (int co = 0; co < C1N; co++) {
            float v0 = fmaxf(acc0[co]*ssc2[co] + sbi2[co], 0.f);
            float v1 = fmaxf(acc1[co]*ssc2[co] + sbi2[co], 0.f);
            g_y2[(((size_t)b*C1N + co)*TT + t)*F2 + fp] = fmaxf(v0, v1);
        }
    }
}

// ---------------- K3: conv3(5->11) + BN + ReLU + maxpool + transpose (R5) --
__global__ void k_conv3pool(const float* __restrict__ w, const float* __restrict__ cb,
                            const float* __restrict__ bg, const float* __restrict__ bbt,
                            const float* __restrict__ bm, const float* __restrict__ bv) {
    __shared__ float sw[C2N*C1N*9];   // 495 floats
    __shared__ float ssc[C2N], sbi[C2N];
    for (int i = threadIdx.x; i < C2N*C1N*9; i += blockDim.x) sw[i] = w[i];
    if (threadIdx.x < C2N) {
        float sc = bg[threadIdx.x] * rsqrtf(bv[threadIdx.x] + BNEPS);
        ssc[threadIdx.x] = sc;
        sbi[threadIdx.x] = (cb[threadIdx.x] - bm[threadIdx.x]) * sc + bbt[threadIdx.x];
    }
    __syncthreads();
    int idx = blockIdx.x * blockDim.x + threadIdx.x;
    if (idx >= BB*TT*F3) return;
    int fp = idx % F3;
    int t = (idx / F3) % TT;
    int b = idx / (F3*TT);
    float acc0[C2N], acc1[C2N];
    #pragma unroll
    for (int c = 0; c < C2N; c++) { acc0[c] = 0.f; acc1[c] = 0.f; }
    #pragma unroll
    for (int ci = 0; ci < C1N; ci++) {
        const float* base = g_y2 + ((size_t)b*C1N + ci)*TT*F2;
        float patch[3][4];
        #pragma unroll
        for (int dt = 0; dt < 3; dt++) {
            int tt = t + dt - 1;
            #pragma unroll
            for (int df = 0; df < 4; df++) {
                int ff = 2*fp + df - 1;
                patch[dt][df] = (tt >= 0 && tt < TT && ff >= 0 && ff < F2) ? base[tt*F2 + ff] : 0.f;
            }
        }
        #pragma unroll
        for (int co = 0; co < C2N; co++) {
            const float* wp = &sw[(co*C1N + ci)*9];
            #pragma unroll
            for (int dt = 0; dt < 3; dt++) {
                #pragma unroll
                for (int df = 0; df < 3; df++) {
                    float wv_ = wp[dt*3 + df];
                    acc0[co] = fmaf(patch[dt][df],     wv_, acc0[co]);
                    acc1[co] = fmaf(patch[dt][df + 1], wv_, acc1[co]);
                }
            }
        }
    }
    size_t rowbase = ((size_t)b*TT + t)*FEATP;
    #pragma unroll
    for (int co = 0; co < C2N; co++) {
        float v0 = fmaxf(acc0[co]*ssc[co] + sbi[co], 0.f);
        float v1 = fmaxf(acc1[co]*ssc[co] + sbi[co], 0.f);
        g_x627[rowbase + co*F3 + fp] = fmaxf(v0, v1);
    }
    // zero the 13 pad columns (627..639) of this row
    if (fp < FEATP - FEAT) g_x627[rowbase + FEAT + fp] = 0.f;
}

// ---------------- K4: fc GEMM (20480 x 640p) @ (640p x 88) + bias (R5) -----
__global__ __launch_bounds__(128) void k_fc(const float* __restrict__ bias) {
    __shared__ float sA[2][64][33];
    __shared__ float sW[2][OFN][33];
    const int m0 = blockIdx.x * 64;
    const int tid = threadIdx.x;
    const int tx = tid % 8;       // cols tx + 8*j, j=0..10
    const int ty = tid / 8;       // 0..15 -> rows 4*ty .. 4*ty+3

    float acc[4][11];
    #pragma unroll
    for (int r = 0; r < 4; r++)
        #pragma unroll
        for (int j = 0; j < 11; j++) acc[r][j] = 0.f;

    float4 pa[4];
    float4 pw[6];

    {
        #pragma unroll
        for (int u = 0; u < 4; u++) {
            int id = tid + 128*u, row = id >> 3, ks = id & 7;
            pa[u] = *(const float4*)(g_x627 + (size_t)(m0 + row)*FEATP + 4*ks);
        }
        #pragma unroll
        for (int u = 0; u < 6; u++) {
            int id = tid + 128*u;
            if (id < 704) {
                int row = id >> 3, ks = id & 7;
                pw[u] = *(const float4*)(g_wfc + (size_t)row*FEATP + 4*ks);
            }
        }
        #pragma unroll
        for (int u = 0; u < 4; u++) {
            int id = tid + 128*u, row = id >> 3, ks = id & 7;
            sA[0][row][4*ks+0] = pa[u].x; sA[0][row][4*ks+1] = pa[u].y;
            sA[0][row][4*ks+2] = pa[u].z; sA[0][row][4*ks+3] = pa[u].w;
        }
        #pragma unroll
        for (int u = 0; u < 6; u++) {
            int id = tid + 128*u;
            if (id < 704) {
                int row = id >> 3, ks = id & 7;
                sW[0][row][4*ks+0] = pw[u].x; sW[0][row][4*ks+1] = pw[u].y;
                sW[0][row][4*ks+2] = pw[u].z; sW[0][row][4*ks+3] = pw[u].w;
            }
        }
    }
    __syncthreads();

    const int NIT = FEATP / 32;   // 20
    for (int it = 0; it < NIT; it++) {
        const int buf = it & 1;
        if (it + 1 < NIT) {
            const int k0 = (it + 1) * 32;
            #pragma unroll
            for (int u = 0; u < 4; u++) {
                int id = tid + 128*u, row = id >> 3, ks = id & 7;
                pa[u] = *(const float4*)(g_x627 + (size_t)(m0 + row)*FEATP + k0 + 4*ks);
            }
            #pragma unroll
            for (int u = 0; u < 6; u++) {
                int id = tid + 128*u;
                if (id < 704) {
                    int row = id >> 3, ks = id & 7;
                    pw[u] = *(const float4*)(g_wfc + (size_t)row*FEATP + k0 + 4*ks);
                }
            }
        }
        #pragma unroll 8
        for (int kk = 0; kk < 32; kk++) {
            float a0 = sA[buf][4*ty+0][kk];
            float a1 = sA[buf][4*ty+1][kk];
            float a2 = sA[buf][4*ty+2][kk];
            float a3 = sA[buf][4*ty+3][kk];
            #pragma unroll
            for (int j = 0; j < 11; j++) {
                float wv_ = sW[buf][tx + 8*j][kk];
                acc[0][j] = fmaf(a0, wv_, acc[0][j]);
                acc[1][j] = fmaf(a1, wv_, acc[1][j]);
                acc[2][j] = fmaf(a2, wv_, acc[2][j]);
                acc[3][j] = fmaf(a3, wv_, acc[3][j]);
            }
        }
        if (it + 1 < NIT) {
            const int nb = buf ^ 1;
            #pragma unroll
            for (int u = 0; u < 4; u++) {
                int id = tid + 128*u, row = id >> 3, ks = id & 7;
                sA[nb][row][4*ks+0] = pa[u].x; sA[nb][row][4*ks+1] = pa[u].y;
                sA[nb][row][4*ks+2] = pa[u].z; sA[nb][row][4*ks+3] = pa[u].w;
            }
            #pragma unroll
            for (int u = 0; u < 6; u++) {
                int id = tid + 128*u;
                if (id < 704) {
                    int row = id >> 3, ks = id & 7;
                    sW[nb][row][4*ks+0] = pw[u].x; sW[nb][row][4*ks+1] = pw[u].y;
                    sW[nb][row][4*ks+2] = pw[u].z; sW[nb][row][4*ks+3] = pw[u].w;
                }
            }
        }
        __syncthreads();
    }

    #pragma unroll
    for (int j = 0; j < 11; j++) {
        float bj = bias[tx + 8*j];
        #pragma unroll
        for (int r = 0; r < 4; r++)
            g_x88[(size_t)(m0 + 4*ty + r)*OFN + tx + 8*j] = acc[r][j] + bj;
    }
}

// ---------------- K5: qkv GEMM (20480 x 88) @ (88 x 144)  (R5) -------------
__global__ void k_qkv(const float* __restrict__ wq, const float* __restrict__ wk,
                      const float* __restrict__ wv) {
    __shared__ float sA[32][45];
    __shared__ float sW[144][45];
    int m0 = blockIdx.x * 32;
    int tx = threadIdx.x % 16;
    int ty = threadIdx.x / 16;
    float acc[2][9];
    #pragma unroll
    for (int r = 0; r < 2; r++)
        #pragma unroll
        for (int j = 0; j < 9; j++) acc[r][j] = 0.f;

    for (int k0 = 0; k0 < OFN; k0 += 44) {
        for (int i = threadIdx.x; i < 32*44; i += 256) {
            int rr = i / 44, kk = i % 44;
            sA[rr][kk] = g_x88[(size_t)(m0 + rr)*OFN + k0 + kk];
        }
        for (int i = threadIdx.x; i < 144*44; i += 256) {
            int n = i / 44, kk = i % 44;
            int kg = k0 + kk;
            float val;
            if (n < 48)      val = wq[n*OFN + kg];
            else if (n < 96) val = wk[(n - 48)*OFN + kg];
            else             val = wv[(n - 96)*OFN + kg];
            sW[n][kk] = val;
        }
        __syncthreads();
        #pragma unroll 11
        for (int kk = 0; kk < 44; kk++) {
            float a0 = sA[2*ty][kk], a1 = sA[2*ty + 1][kk];
            #pragma unroll
            for (int j = 0; j < 9; j++) {
                float wv_ = sW[tx + 16*j][kk];
                acc[0][j] = fmaf(a0, wv_, acc[0][j]);
                acc[1][j] = fmaf(a1, wv_, acc[1][j]);
            }
        }
        __syncthreads();
    }
    #pragma unroll
    for (int r = 0; r < 2; r++)
        #pragma unroll
        for (int j = 0; j < 9; j++)
            g_qkv[(size_t)(m0 + 2*ty + r)*144 + tx + 16*j] = acc[r][j];
}

// ---------------- K6: sliding-window attention -----------------------------
#define TTILE 64
__global__ void k_attn(const float* __restrict__ rel, float* __restrict__ a_out) {
    __shared__ float ks[TTILE + 30][49];
    __shared__ float vs[TTILE + 30][49];
    __shared__ float srel[MCN*KW];
    int b  = blockIdx.x / (TT / TTILE);
    int t0 = (blockIdx.x % (TT / TTILE)) * TTILE;

    for (int i = threadIdx.x; i < MCN*KW; i += 256) srel[i] = rel[i];
    for (int i = threadIdx.x; i < (TTILE + 30)*MCN; i += 256) {
        int row = i / MCN, col = i % MCN;
        int t = t0 + row - PADW;
        float kv = 0.f, vv = 0.f;
        if (t >= 0 && t < TT) {
            const float* p = g_qkv + ((size_t)b*TT + t)*144;
            kv = p[48 + col];
            vv = p[96 + col];
        }
        ks[row][col] = kv;
        vs[row][col] = vv;
    }
    __syncthreads();

    for (int item = threadIdx.x; item < TTILE*GN; item += 256) {
        int g  = item % GN;
        int tl = item / GN;
        int t = t0 + tl;
        int gd = g * DH;
        const float* qp = g_qkv + ((size_t)b*TT + t)*144 + gd;
        float q0 = qp[0], q1 = qp[1], q2 = qp[2], q3 = qp[3], q4 = qp[4], q5 = qp[5];

        float e[KW];
        float emax = -1e30f;
        #pragma unroll
        for (int kk = 0; kk < KW; kk++) {
            float s;
            s =          q0 * (ks[tl + kk][gd + 0] + srel[(gd + 0)*KW + kk]);
            s = fmaf(q1, (ks[tl + kk][gd + 1] + srel[(gd + 1)*KW + kk]), s);
            s = fmaf(q2, (ks[tl + kk][gd + 2] + srel[(gd + 2)*KW + kk]), s);
            s = fmaf(q3, (ks[tl + kk][gd + 3] + srel[(gd + 3)*KW + kk]), s);
            s = fmaf(q4, (ks[tl + kk][gd + 4] + srel[(gd + 4)*KW + kk]), s);
            s = fmaf(q5, (ks[tl + kk][gd + 5] + srel[(gd + 5)*KW + kk]), s);
            e[kk] = s;
            emax = fmaxf(emax, s);
        }
        float sum = 0.f;
        #pragma unroll
        for (int kk = 0; kk < KW; kk++) {
            e[kk] = __expf(e[kk] - emax);
            sum += e[kk];
        }
        float inv = 1.f / sum;
        float o0 = 0.f, o1 = 0.f, o2 = 0.f, o3 = 0.f, o4 = 0.f, o5 = 0.f;
        float* ap = a_out + (((size_t)b*TT + t)*GN + g)*KW;
        #pragma unroll
        for (int kk = 0; kk < KW; kk++) {
            float p = e[kk] * inv;
            ap[kk] = p;
            o0 = fmaf(p, vs[tl + kk][gd + 0], o0);
            o1 = fmaf(p, vs[tl + kk][gd + 1], o1);
            o2 = fmaf(p, vs[tl + kk][gd + 2], o2);
            o3 = fmaf(p, vs[tl + kk][gd + 3], o3);
            o4 = fmaf(p, vs[tl + kk][gd + 4], o4);
            o5 = fmaf(p, vs[tl + kk][gd + 5], o5);
        }
        float* op = g_out48 + ((size_t)b*TT + t)*MCN + gd;
        op[0] = o0; op[1] = o1; op[2] = o2; op[3] = o3; op[4] = o4; op[5] = o5;
    }
}

// ---------------- K7: LayerNorm(48) + linear(48->88) + sigmoid -------------
__global__ void k_lnout(const float* __restrict__ lng, const float* __restrict__ lnb,
                        const float* __restrict__ lw, const float* __restrict__ lb,
                        float* __restrict__ out) {
    __shared__ float slw[OFN*49];
    __shared__ float sh[8][MCN];
    __shared__ float sg[MCN], sb[MCN], slb[OFN];
    for (int i = threadIdx.x; i < OFN*MCN; i += 256) {
        int n = i / MCN, j = i % MCN;
        slw[n*49 + j] = lw[i];
    }
    if (threadIdx.x < MCN) { sg[threadIdx.x] = lng[threadIdx.x]; sb[threadIdx.x] = lnb[threadIdx.x]; }
    if (threadIdx.x < OFN) slb[threadIdx.x] = lb[threadIdx.x];
    __syncthreads();

    int warp = threadIdx.x / 32, lane = threadIdx.x % 32;
    int row = blockIdx.x * 8 + warp;
    const float* xp = g_out48 + (size_t)row*MCN;
    float x0 = xp[lane];
    float x1 = (lane < 16) ? xp[lane + 32] : 0.f;
    float s  = x0 + x1;
    float s2 = x0*x0 + x1*x1;
    #pragma unroll
    for (int off = 16; off > 0; off >>= 1) {
        s  += __shfl_xor_sync(0xFFFFFFFFu, s,  off);
        s2 += __shfl_xor_sync(0xFFFFFFFFu, s2, off);
    }
    float mu = s * (1.f/48.f);
    float var = s2 * (1.f/48.f) - mu*mu;
    float rstd = rsqrtf(var + 1e-5f);
    sh[warp][lane] = (x0 - mu) * rstd * sg[lane] + sb[lane];
    if (lane < 16) sh[warp][lane + 32] = (x1 - mu) * rstd * sg[lane + 32] + sb[lane + 32];
    __syncwarp();

    #pragma unroll
    for (int jj = 0; jj < 3; jj++) {
        int n = lane + 32*jj;
        if (n < OFN) {
            float z = slb[n];
            #pragma unroll
            for (int j = 0; j < MCN; j++)
                z = fmaf(sh[warp][j], slw[n*49 + j], z);
            out[(size_t)row*OFN + n] = 1.f / (1.f + __expf(-z));
        }
    }
}

// ---------------- launch ---------------------------------------------------
extern "C" void kernel_launch(void* const* d_in, const int* in_sizes, int n_in,
                              void* d_out, int out_size) {
    const float* spec  = (const float*)d_in[0];
    const float* c1_w  = (const float*)d_in[1];
    const float* c1_b  = (const float*)d_in[2];
    const float* bn1_g = (const float*)d_in[3];
    const float* bn1_b = (const float*)d_in[4];
    const float* bn1_m = (const float*)d_in[5];
    const float* bn1_v = (const float*)d_in[6];
    const float* c2_w  = (const float*)d_in[7];
    const float* c2_b  = (const float*)d_in[8];
    const float* bn2_g = (const float*)d_in[9];
    const float* bn2_b = (const float*)d_in[10];
    const float* bn2_m = (const float*)d_in[11];
    const float* bn2_v = (const float*)d_in[12];
    const float* c3_w  = (const float*)d_in[13];
    const float* c3_b  = (const float*)d_in[14];
    const float* bn3_g = (const float*)d_in[15];
    const float* bn3_b = (const float*)d_in[16];
    const float* bn3_m = (const float*)d_in[17];
    const float* bn3_v = (const float*)d_in[18];
    const float* fc_w  = (const float*)d_in[19];
    const float* fc_b  = (const float*)d_in[20];
    const float* wq    = (const float*)d_in[21];
    const float* wk    = (const float*)d_in[22];
    const float* wv    = (const float*)d_in[23];
    const float* rel   = (const float*)d_in[24];
    const float* ln_g  = (const float*)d_in[25];
    const float* ln_b  = (const float*)d_in[26];
    const float* lin_w = (const float*)d_in[27];
    const float* lin_b = (const float*)d_in[28];

    float* out   = (float*)d_out;                 // frame_pred (B,T,88)
    float* a_out = out + FRAME_ELEMS;             // a (B,T,8,31)

    static bool attr_set = false;
    if (!attr_set) {
        cudaFuncSetAttribute(k_conv12, cudaFuncAttributeMaxDynamicSharedMemorySize,
                             SMEM12_BYTES);
        attr_set = true;
    }

    k_repack_w<<<(OFN*FEATP + 255)/256, 256>>>(fc_w);
    k_conv12<<<BB*(TT/TTC), 256, SMEM12_BYTES>>>(spec,
        c1_w, c1_b, bn1_g, bn1_b, bn1_m, bn1_v,
        c2_w, c2_b, bn2_g, bn2_b, bn2_m, bn2_v);
    int n3 = BB*TT*F3;
    k_conv3pool<<<(n3 + 255)/256, 256>>>(c3_w, c3_b, bn3_g, bn3_b, bn3_m, bn3_v);
    k_fc<<<(BB*TT)/64, 128>>>(fc_b);
    k_qkv<<<(BB*TT)/32, 256>>>(wq, wk, wv);
    k_attn<<<BB*(TT/TTILE), 256>>>(rel, a_out);
    k_lnout<<<(BB*TT)/8, 256>>>(ln_g, ln_b, lin_w, lin_b, out);
}

// round 12
// speedup vs baseline: 1.1350x; 1.0237x over previous
#include <cuda_runtime.h>

#define BB 8
#define TT 2560
#define FF 229
#define C1N 5
#define C2N 11
#define F2 114
#define F3 57
#define FEAT 627       // C2N * F3
#define FEATP 640      // padded K for fc (float4-aligned)
#define OFN 88
#define MCN 48
#define GN 8
#define DH 6
#define KW 31
#define PADW 15
#define BNEPS 1e-5f
#define FRAME_ELEMS (BB*TT*OFN)

// ---------------- scratch (device globals; no allocation allowed) ----------
__device__ float g_y1[(size_t)BB*C1N*TT*FF];     // conv1 out  (B,C1,T,F)
__device__ float g_y2[(size_t)BB*C1N*TT*F2];     // conv2+pool (B,C1,T,F2)
__device__ float g_x627[(size_t)BB*TT*FEATP];    // conv3+pool, (B*T, 640) padded
__device__ float g_wfc[(size_t)OFN*FEATP];       // repacked fc_w (88, 640) padded
__device__ float g_x88[(size_t)BB*TT*OFN];       // fc out (B*T, 88)
__device__ float g_qkv[(size_t)BB*TT*144];       // q|k|v (B*T, 144)

// ---------------- K0: repack fc weights into padded layout -----------------
__global__ void k_repack_w(const float* __restrict__ fw) {
    int idx = blockIdx.x * blockDim.x + threadIdx.x;
    if (idx >= OFN*FEATP) return;
    int n = idx / FEATP, k = idx % FEATP;
    g_wfc[idx] = (k < FEAT) ? fw[n*FEAT + k] : 0.f;
}

// ---------------- K1: conv1(1->5) + BN + ReLU ------------------------------
__global__ void k_conv1(const float* __restrict__ spec, const float* __restrict__ w,
                        const float* __restrict__ cb, const float* __restrict__ bg,
                        const float* __restrict__ bbt, const float* __restrict__ bm,
                        const float* __restrict__ bv) {
    __shared__ float sw[C1N*9];
    __shared__ float ssc[C1N], sbi[C1N];
    for (int i = threadIdx.x; i < C1N*9; i += blockDim.x) sw[i] = w[i];
    if (threadIdx.x < C1N) {
        float sc = bg[threadIdx.x] * rsqrtf(bv[threadIdx.x] + BNEPS);
        ssc[threadIdx.x] = sc;
        sbi[threadIdx.x] = (cb[threadIdx.x] - bm[threadIdx.x]) * sc + bbt[threadIdx.x];
    }
    __syncthreads();
    int idx = blockIdx.x * blockDim.x + threadIdx.x;
    if (idx >= BB*TT*FF) return;
    int f = idx % FF;
    int t = (idx / FF) % TT;
    int b = idx / (FF*TT);
    const float* sp = spec + (size_t)b * TT * FF;
    float in[3][3];
    #pragma unroll
    for (int dt = 0; dt < 3; dt++) {
        int tt = t + dt - 1;
        #pragma unroll
        for (int df = 0; df < 3; df++) {
            int ff = f + df - 1;
            in[dt][df] = (tt >= 0 && tt < TT && ff >= 0 && ff < FF) ? sp[tt*FF + ff] : 0.f;
        }
    }
    #pragma unroll
    for (int c = 0; c < C1N; c++) {
        float acc = 0.f;
        #pragma unroll
        for (int k9 = 0; k9 < 9; k9++)
            acc = fmaf(in[k9/3][k9%3], sw[c*9 + k9], acc);
        float val = acc * ssc[c] + sbi[c];
        g_y1[(((size_t)b*C1N + c)*TT + t)*FF + f] = fmaxf(val, 0.f);
    }
}

// ---------------- K2: conv2(5->5) + BN + ReLU + maxpool(W/2)  (R5 scalar) --
__global__ void k_conv2pool(const float* __restrict__ w, const float* __restrict__ cb,
                            const float* __restrict__ bg, const float* __restrict__ bbt,
                            const float* __restrict__ bm, const float* __restrict__ bv) {
    __shared__ float sw[C1N*C1N*9];
    __shared__ float ssc[C1N], sbi[C1N];
    for (int i = threadIdx.x; i < C1N*C1N*9; i += blockDim.x) sw[i] = w[i];
    if (threadIdx.x < C1N) {
        float sc = bg[threadIdx.x] * rsqrtf(bv[threadIdx.x] + BNEPS);
        ssc[threadIdx.x] = sc;
        sbi[threadIdx.x] = (cb[threadIdx.x] - bm[threadIdx.x]) * sc + bbt[threadIdx.x];
    }
    __syncthreads();
    int idx = blockIdx.x * blockDim.x + threadIdx.x;
    if (idx >= BB*TT*F2) return;
    int fp = idx % F2;
    int t = (idx / F2) % TT;
    int b = idx / (F2*TT);
    float acc0[C1N], acc1[C1N];
    #pragma unroll
    for (int c = 0; c < C1N; c++) { acc0[c] = 0.f; acc1[c] = 0.f; }
    #pragma unroll
    for (int ci = 0; ci < C1N; ci++) {
        const float* base = g_y1 + ((size_t)b*C1N + ci)*TT*FF;
        float patch[3][4];
        #pragma unroll
        for (int dt = 0; dt < 3; dt++) {
            int tt = t + dt - 1;
            #pragma unroll
            for (int df = 0; df < 4; df++) {
                int ff = 2*fp + df - 1;
                patch[dt][df] = (tt >= 0 && tt < TT && ff >= 0 && ff < FF) ? base[tt*FF + ff] : 0.f;
            }
        }
        #pragma unroll
        for (int co = 0; co < C1N; co++) {
            const float* wp = &sw[(co*C1N + ci)*9];
            #pragma unroll
            for (int dt = 0; dt < 3; dt++) {
                #pragma unroll
                for (int df = 0; df < 3; df++) {
                    float wv_ = wp[dt*3 + df];
                    acc0[co] = fmaf(patch[dt][df],     wv_, acc0[co]);
                    acc1[co] = fmaf(patch[dt][df + 1], wv_, acc1[co]);
                }
            }
        }
    }
    #pragma unroll
    for (int co = 0; co < C1N; co++) {
        float v0 = fmaxf(acc0[co]*ssc[co] + sbi[co], 0.f);
        float v1 = fmaxf(acc1[co]*ssc[co] + sbi[co], 0.f);
        g_y2[(((size_t)b*C1N + co)*TT + t)*F2 + fp] = fmaxf(v0, v1);
    }
}

// ---------------- K3: conv3(5->11) + BN + ReLU + maxpool + transpose (R5) --
__global__ void k_conv3pool(const float* __restrict__ w, const float* __restrict__ cb,
                            const float* __restrict__ bg, const float* __restrict__ bbt,
                            const float* __restrict__ bm, const float* __restrict__ bv) {
    __shared__ float sw[C2N*C1N*9];   // 495 floats
    __shared__ float ssc[C2N], sbi[C2N];
    for (int i = threadIdx.x; i < C2N*C1N*9; i += blockDim.x) sw[i] = w[i];
    if (threadIdx.x < C2N) {
        float sc = bg[threadIdx.x] * rsqrtf(bv[threadIdx.x] + BNEPS);
        ssc[threadIdx.x] = sc;
        sbi[threadIdx.x] = (cb[threadIdx.x] - bm[threadIdx.x]) * sc + bbt[threadIdx.x];
    }
    __syncthreads();
    int idx = blockIdx.x * blockDim.x + threadIdx.x;
    if (idx >= BB*TT*F3) return;
    int fp = idx % F3;
    int t = (idx / F3) % TT;
    int b = idx / (F3*TT);
    float acc0[C2N], acc1[C2N];
    #pragma unroll
    for (int c = 0; c < C2N; c++) { acc0[c] = 0.f; acc1[c] = 0.f; }
    #pragma unroll
    for (int ci = 0; ci < C1N; ci++) {
        const float* base = g_y2 + ((size_t)b*C1N + ci)*TT*F2;
        float patch[3][4];
        #pragma unroll
        for (int dt = 0; dt < 3; dt++) {
            int tt = t + dt - 1;
            #pragma unroll
            for (int df = 0; df < 4; df++) {
                int ff = 2*fp + df - 1;
                patch[dt][df] = (tt >= 0 && tt < TT && ff >= 0 && ff < F2) ? base[tt*F2 + ff] : 0.f;
            }
        }
        #pragma unroll
        for (int co = 0; co < C2N; co++) {
            const float* wp = &sw[(co*C1N + ci)*9];
            #pragma unroll
            for (int dt = 0; dt < 3; dt++) {
                #pragma unroll
                for (int df = 0; df < 3; df++) {
                    float wv_ = wp[dt*3 + df];
                    acc0[co] = fmaf(patch[dt][df],     wv_, acc0[co]);
                    acc1[co] = fmaf(patch[dt][df + 1], wv_, acc1[co]);
                }
            }
        }
    }
    size_t rowbase = ((size_t)b*TT + t)*FEATP;
    #pragma unroll
    for (int co = 0; co < C2N; co++) {
        float v0 = fmaxf(acc0[co]*ssc[co] + sbi[co], 0.f);
        float v1 = fmaxf(acc1[co]*ssc[co] + sbi[co], 0.f);
        g_x627[rowbase + co*F3 + fp] = fmaxf(v0, v1);
    }
    if (fp < FEATP - FEAT) g_x627[rowbase + FEAT + fp] = 0.f;
}

// ---------------- K4: fc GEMM (20480 x 640p) @ (640p x 88) + bias (R5) -----
__global__ __launch_bounds__(128) void k_fc(const float* __restrict__ bias) {
    __shared__ float sA[2][64][33];
    __shared__ float sW[2][OFN][33];
    const int m0 = blockIdx.x * 64;
    const int tid = threadIdx.x;
    const int tx = tid % 8;
    const int ty = tid / 8;

    float acc[4][11];
    #pragma unroll
    for (int r = 0; r < 4; r++)
        #pragma unroll
        for (int j = 0; j < 11; j++) acc[r][j] = 0.f;

    float4 pa[4];
    float4 pw[6];

    {
        #pragma unroll
        for (int u = 0; u < 4; u++) {
            int id = tid + 128*u, row = id >> 3, ks = id & 7;
            pa[u] = *(const float4*)(g_x627 + (size_t)(m0 + row)*FEATP + 4*ks);
        }
        #pragma unroll
        for (int u = 0; u < 6; u++) {
            int id = tid + 128*u;
            if (id < 704) {
                int row = id >> 3, ks = id & 7;
                pw[u] = *(const float4*)(g_wfc + (size_t)row*FEATP + 4*ks);
            }
        }
        #pragma unroll
        for (int u = 0; u < 4; u++) {
            int id = tid + 128*u, row = id >> 3, ks = id & 7;
            sA[0][row][4*ks+0] = pa[u].x; sA[0][row][4*ks+1] = pa[u].y;
            sA[0][row][4*ks+2] = pa[u].z; sA[0][row][4*ks+3] = pa[u].w;
        }
        #pragma unroll
        for (int u = 0; u < 6; u++) {
            int id = tid + 128*u;
            if (id < 704) {
                int row = id >> 3, ks = id & 7;
                sW[0][row][4*ks+0] = pw[u].x; sW[0][row][4*ks+1] = pw[u].y;
                sW[0][row][4*ks+2] = pw[u].z; sW[0][row][4*ks+3] = pw[u].w;
            }
        }
    }
    __syncthreads();

    const int NIT = FEATP / 32;   // 20
    for (int it = 0; it < NIT; it++) {
        const int buf = it & 1;
        if (it + 1 < NIT) {
            const int k0 = (it + 1) * 32;
            #pragma unroll
            for (int u = 0; u < 4; u++) {
                int id = tid + 128*u, row = id >> 3, ks = id & 7;
                pa[u] = *(const float4*)(g_x627 + (size_t)(m0 + row)*FEATP + k0 + 4*ks);
            }
            #pragma unroll
            for (int u = 0; u < 6; u++) {
                int id = tid + 128*u;
                if (id < 704) {
                    int row = id >> 3, ks = id & 7;
                    pw[u] = *(const float4*)(g_wfc + (size_t)row*FEATP + k0 + 4*ks);
                }
            }
        }
        #pragma unroll 8
        for (int kk = 0; kk < 32; kk++) {
            float a0 = sA[buf][4*ty+0][kk];
            float a1 = sA[buf][4*ty+1][kk];
            float a2 = sA[buf][4*ty+2][kk];
            float a3 = sA[buf][4*ty+3][kk];
            #pragma unroll
            for (int j = 0; j < 11; j++) {
                float wv_ = sW[buf][tx + 8*j][kk];
                acc[0][j] = fmaf(a0, wv_, acc[0][j]);
                acc[1][j] = fmaf(a1, wv_, acc[1][j]);
                acc[2][j] = fmaf(a2, wv_, acc[2][j]);
                acc[3][j] = fmaf(a3, wv_, acc[3][j]);
            }
        }
        if (it + 1 < NIT) {
            const int nb = buf ^ 1;
            #pragma unroll
            for (int u = 0; u < 4; u++) {
                int id = tid + 128*u, row = id >> 3, ks = id & 7;
                sA[nb][row][4*ks+0] = pa[u].x; sA[nb][row][4*ks+1] = pa[u].y;
                sA[nb][row][4*ks+2] = pa[u].z; sA[nb][row][4*ks+3] = pa[u].w;
            }
            #pragma unroll
            for (int u = 0; u < 6; u++) {
                int id = tid + 128*u;
                if (id < 704) {
                    int row = id >> 3, ks = id & 7;
                    sW[nb][row][4*ks+0] = pw[u].x; sW[nb][row][4*ks+1] = pw[u].y;
                    sW[nb][row][4*ks+2] = pw[u].z; sW[nb][row][4*ks+3] = pw[u].w;
                }
            }
        }
        __syncthreads();
    }

    #pragma unroll
    for (int j = 0; j < 11; j++) {
        float bj = bias[tx + 8*j];
        #pragma unroll
        for (int r = 0; r < 4; r++)
            g_x88[(size_t)(m0 + 4*ty + r)*OFN + tx + 8*j] = acc[r][j] + bj;
    }
}

// ---------------- K5: qkv GEMM (20480 x 88) @ (88 x 144)  (R5) -------------
__global__ void k_qkv(const float* __restrict__ wq, const float* __restrict__ wk,
                      const float* __restrict__ wv) {
    __shared__ float sA[32][45];
    __shared__ float sW[144][45];
    int m0 = blockIdx.x * 32;
    int tx = threadIdx.x % 16;
    int ty = threadIdx.x / 16;
    float acc[2][9];
    #pragma unroll
    for (int r = 0; r < 2; r++)
        #pragma unroll
        for (int j = 0; j < 9; j++) acc[r][j] = 0.f;

    for (int k0 = 0; k0 < OFN; k0 += 44) {
        for (int i = threadIdx.x; i < 32*44; i += 256) {
            int rr = i / 44, kk = i % 44;
            sA[rr][kk] = g_x88[(size_t)(m0 + rr)*OFN + k0 + kk];
        }
        for (int i = threadIdx.x; i < 144*44; i += 256) {
            int n = i / 44, kk = i % 44;
            int kg = k0 + kk;
            float val;
            if (n < 48)      val = wq[n*OFN + kg];
            else if (n < 96) val = wk[(n - 48)*OFN + kg];
            else             val = wv[(n - 96)*OFN + kg];
            sW[n][kk] = val;
        }
        __syncthreads();
        #pragma unroll 11
        for (int kk = 0; kk < 44; kk++) {
            float a0 = sA[2*ty][kk], a1 = sA[2*ty + 1][kk];
            #pragma unroll
            for (int j = 0; j < 9; j++) {
                float wv_ = sW[tx + 16*j][kk];
                acc[0][j] = fmaf(a0, wv_, acc[0][j]);
                acc[1][j] = fmaf(a1, wv_, acc[1][j]);
            }
        }
        __syncthreads();
    }
    #pragma unroll
    for (int r = 0; r < 2; r++)
        #pragma unroll
        for (int j = 0; j < 9; j++)
            g_qkv[(size_t)(m0 + 2*ty + r)*144 + tx + 16*j] = acc[r][j];
}

// ---------------- K6: sliding-window attention + LN + linear + sigmoid -----
// dynamic smem layout (floats):
//   phase 1: ks[94*49] @0 | vs[94*49] @4606 | srel[48*31] @9212 | sout[64*48] @10700
//   phase 2: slw[88*49] @0 (over ks/vs) | sh[8*48] @9212 (over srel) | sout kept
#define TTILE 64
#define ATTN_SM_FLOATS (10700 + 64*48)          // 13772
#define ATTN_SM_BYTES  (ATTN_SM_FLOATS * 4)     // 55088
__global__ __launch_bounds__(256) void k_attn_ln(
        const float* __restrict__ rel,
        const float* __restrict__ lng, const float* __restrict__ lnb,
        const float* __restrict__ lw,  const float* __restrict__ lb,
        float* __restrict__ a_out, float* __restrict__ out) {
    extern __shared__ float dsm[];
    float* ks   = dsm;            // [94][49]
    float* vs   = dsm + 4606;     // [94][49]
    float* srel = dsm + 9212;     // [48*31]
    float* sout = dsm + 10700;    // [64][48]
    __shared__ float sg[MCN], sb[MCN], slb[OFN];

    int b  = blockIdx.x / (TT / TTILE);
    int t0 = (blockIdx.x % (TT / TTILE)) * TTILE;

    if (threadIdx.x < MCN) { sg[threadIdx.x] = lng[threadIdx.x]; sb[threadIdx.x] = lnb[threadIdx.x]; }
    if (threadIdx.x < OFN) slb[threadIdx.x] = lb[threadIdx.x];

    for (int i = threadIdx.x; i < MCN*KW; i += 256) srel[i] = rel[i];
    for (int i = threadIdx.x; i < (TTILE + 30)*MCN; i += 256) {
        int row = i / MCN, col = i % MCN;
        int t = t0 + row - PADW;
        float kv = 0.f, vv = 0.f;
        if (t >= 0 && t < TT) {
            const float* p = g_qkv + ((size_t)b*TT + t)*144;
            kv = p[48 + col];
            vv = p[96 + col];
        }
        ks[row*49 + col] = kv;
        vs[row*49 + col] = vv;
    }
    __syncthreads();

    for (int item = threadIdx.x; item < TTILE*GN; item += 256) {
        int g  = item % GN;
        int tl = item / GN;
        int t = t0 + tl;
        int gd = g * DH;
        const float* qp = g_qkv + ((size_t)b*TT + t)*144 + gd;
        float q0 = qp[0], q1 = qp[1], q2 = qp[2], q3 = qp[3], q4 = qp[4], q5 = qp[5];

        float e[KW];
        float emax = -1e30f;
        #pragma unroll
        for (int kk = 0; kk < KW; kk++) {
            const float* kr = &ks[(tl + kk)*49 + gd];
            float s;
            s =          q0 * (kr[0] + srel[(gd + 0)*KW + kk]);
            s = fmaf(q1, (kr[1] + srel[(gd + 1)*KW + kk]), s);
            s = fmaf(q2, (kr[2] + srel[(gd + 2)*KW + kk]), s);
            s = fmaf(q3, (kr[3] + srel[(gd + 3)*KW + kk]), s);
            s = fmaf(q4, (kr[4] + srel[(gd + 4)*KW + kk]), s);
            s = fmaf(q5, (kr[5] + srel[(gd + 5)*KW + kk]), s);
            e[kk] = s;
            emax = fmaxf(emax, s);
        }
        float sum = 0.f;
        #pragma unroll
        for (int kk = 0; kk < KW; kk++) {
            e[kk] = __expf(e[kk] - emax);
            sum += e[kk];
        }
        float inv = 1.f / sum;
        float o0 = 0.f, o1 = 0.f, o2 = 0.f, o3 = 0.f, o4 = 0.f, o5 = 0.f;
        float* ap = a_out + (((size_t)b*TT + t)*GN + g)*KW;
        #pragma unroll
        for (int kk = 0; kk < KW; kk++) {
            float p = e[kk] * inv;
            ap[kk] = p;
            const float* vr = &vs[(tl + kk)*49 + gd];
            o0 = fmaf(p, vr[0], o0);
            o1 = fmaf(p, vr[1], o1);
            o2 = fmaf(p, vr[2], o2);
            o3 = fmaf(p, vr[3], o3);
            o4 = fmaf(p, vr[4], o4);
            o5 = fmaf(p, vr[5], o5);
        }
        float* op = &sout[tl*MCN + gd];
        op[0] = o0; op[1] = o1; op[2] = o2; op[3] = o3; op[4] = o4; op[5] = o5;
    }
    __syncthreads();

    // ---- phase 2: LayerNorm(48) + linear(48->88) + sigmoid -----------------
    float* slw = dsm;             // [88][49] (over dead ks/vs)
    float* sh  = dsm + 9212;      // [8][48]  (over dead srel)
    for (int i = threadIdx.x; i < OFN*MCN; i += 256) {
        int n = i / MCN, j = i % MCN;
        slw[n*49 + j] = lw[i];
    }
    __syncthreads();

    int warp = threadIdx.x / 32, lane = threadIdx.x % 32;
    #pragma unroll
    for (int pass = 0; pass < 8; pass++) {
        int lrow = pass*8 + warp;                  // 0..63
        const float* xp = &sout[lrow*MCN];
        float x0 = xp[lane];
        float x1 = (lane < 16) ? xp[lane + 32] : 0.f;
        float s  = x0 + x1;
        float s2 = x0*x0 + x1*x1;
        #pragma unroll
        for (int off = 16; off > 0; off >>= 1) {
            s  += __shfl_xor_sync(0xFFFFFFFFu, s,  off);
            s2 += __shfl_xor_sync(0xFFFFFFFFu, s2, off);
        }
        float mu = s * (1.f/48.f);
        float var = s2 * (1.f/48.f) - mu*mu;
        float rstd = rsqrtf(var + 1e-5f);
        sh[warp*MCN + lane] = (x0 - mu) * rstd * sg[lane] + sb[lane];
        if (lane < 16) sh[warp*MCN + lane + 32] = (x1 - mu) * rstd * sg[lane + 32] + sb[lane + 32];
        __syncwarp();

        size_t rowoff = ((size_t)b*TT + t0 + lrow)*OFN;
        #pragma unroll
        for (int jj = 0; jj < 3; jj++) {
            int n = lane + 32*jj;
            if (n < OFN) {
                float z = slb[n];
                #pragma unroll
                for (int j = 0; j < MCN; j++)
                    z = fmaf(sh[warp*MCN + j], slw[n*49 + j], z);
                out[rowoff + n] = 1.f / (1.f + __expf(-z));
            }
        }
        __syncwarp();
    }
}

// ---------------- launch ---------------------------------------------------
extern "C" void kernel_launch(void* const* d_in, const int* in_sizes, int n_in,
                              void* d_out, int out_size) {
    const float* spec  = (const float*)d_in[0];
    const float* c1_w  = (const float*)d_in[1];
    const float* c1_b  = (const float*)d_in[2];
    const float* bn1_g = (const float*)d_in[3];
    const float* bn1_b = (const float*)d_in[4];
    const float* bn1_m = (const float*)d_in[5];
    const float* bn1_v = (const float*)d_in[6];
    const float* c2_w  = (const float*)d_in[7];
    const float* c2_b  = (const float*)d_in[8];
    const float* bn2_g = (const float*)d_in[9];
    const float* bn2_b = (const float*)d_in[10];
    const float* bn2_m = (const float*)d_in[11];
    const float* bn2_v = (const float*)d_in[12];
    const float* c3_w  = (const float*)d_in[13];
    const float* c3_b  = (const float*)d_in[14];
    const float* bn3_g = (const float*)d_in[15];
    const float* bn3_b = (const float*)d_in[16];
    const float* bn3_m = (const float*)d_in[17];
    const float* bn3_v = (const float*)d_in[18];
    const float* fc_w  = (const float*)d_in[19];
    const float* fc_b  = (const float*)d_in[20];
    const float* wq    = (const float*)d_in[21];
    const float* wk    = (const float*)d_in[22];
    const float* wv    = (const float*)d_in[23];
    const float* rel   = (const float*)d_in[24];
    const float* ln_g  = (const float*)d_in[25];
    const float* ln_b  = (const float*)d_in[26];
    const float* lin_w = (const float*)d_in[27];
    const float* lin_b = (const float*)d_in[28];

    float* out   = (float*)d_out;                 // frame_pred (B,T,88)
    float* a_out = out + FRAME_ELEMS;             // a (B,T,8,31)

    cudaFuncSetAttribute(k_attn_ln, cudaFuncAttributeMaxDynamicSharedMemorySize,
                         ATTN_SM_BYTES);

    k_repack_w<<<(OFN*FEATP + 255)/256, 256>>>(fc_w);
    int n1 = BB*TT*FF;
    k_conv1<<<(n1 + 255)/256, 256>>>(spec, c1_w, c1_b, bn1_g, bn1_b, bn1_m, bn1_v);
    int n2 = BB*TT*F2;
    k_conv2pool<<<(n2 + 255)/256, 256>>>(c2_w, c2_b, bn2_g, bn2_b, bn2_m, bn2_v);
    int n3 = BB*TT*F3;
    k_conv3pool<<<(n3 + 255)/256, 256>>>(c3_w, c3_b, bn3_g, bn3_b, bn3_m, bn3_v);
    k_fc<<<(BB*TT)/64, 128>>>(fc_b);
    k_qkv<<<(BB*TT)/32, 256>>>(wq, wk, wv);
    k_attn_ln<<<BB*(TT/TTILE), 256, ATTN_SM_BYTES>>>(rel, ln_g, ln_b, lin_w, lin_b,
                                                     a_out, out);
}

// round 13
// speedup vs baseline: 1.1835x; 1.0427x over previous
#include <cuda_runtime.h>

#define BB 8
#define TT 2560
#define FF 229
#define C1N 5
#define C2N 11
#define F2 114
#define F3 57
#define FEAT 627       // C2N * F3
#define FEATP 640      // padded K for fc (float4-aligned)
#define OFN 88
#define MCN 48
#define GN 8
#define DH 6
#define KW 31
#define PADW 15
#define BNEPS 1e-5f
#define FRAME_ELEMS (BB*TT*OFN)

// ---------------- scratch (device globals; no allocation allowed) ----------
__device__ float g_y1[(size_t)BB*C1N*TT*FF];     // conv1 out  (B,C1,T,F)
__device__ float g_y2[(size_t)BB*C1N*TT*F2];     // conv2+pool (B,C1,T,F2)
__device__ float g_x627[(size_t)BB*TT*FEATP];    // conv3+pool, (B*T, 640) padded
__device__ float g_wfc[(size_t)OFN*FEATP];       // repacked fc_w (88, 640) padded
__device__ float g_x88[(size_t)BB*TT*OFN];       // fc out (B*T, 88)
__device__ float g_qkv[(size_t)BB*TT*144];       // q|k|v (B*T, 144)
__device__ float g_out48[(size_t)BB*TT*MCN];     // attention out (B*T, 48)

// ---------------- K0: repack fc weights into padded layout -----------------
__global__ void k_repack_w(const float* __restrict__ fw) {
    int idx = blockIdx.x * blockDim.x + threadIdx.x;
    if (idx >= OFN*FEATP) return;
    int n = idx / FEATP, k = idx % FEATP;
    g_wfc[idx] = (k < FEAT) ? fw[n*FEAT + k] : 0.f;
}

// ---------------- K1: conv1(1->5) + BN + ReLU ------------------------------
__global__ void k_conv1(const float* __restrict__ spec, const float* __restrict__ w,
                        const float* __restrict__ cb, const float* __restrict__ bg,
                        const float* __restrict__ bbt, const float* __restrict__ bm,
                        const float* __restrict__ bv) {
    __shared__ float sw[C1N*9];
    __shared__ float ssc[C1N], sbi[C1N];
    for (int i = threadIdx.x; i < C1N*9; i += blockDim.x) sw[i] = w[i];
    if (threadIdx.x < C1N) {
        float sc = bg[threadIdx.x] * rsqrtf(bv[threadIdx.x] + BNEPS);
        ssc[threadIdx.x] = sc;
        sbi[threadIdx.x] = (cb[threadIdx.x] - bm[threadIdx.x]) * sc + bbt[threadIdx.x];
    }
    __syncthreads();
    int idx = blockIdx.x * blockDim.x + threadIdx.x;
    if (idx >= BB*TT*FF) return;
    int f = idx % FF;
    int t = (idx / FF) % TT;
    int b = idx / (FF*TT);
    const float* sp = spec + (size_t)b * TT * FF;
    float in[3][3];
    #pragma unroll
    for (int dt = 0; dt < 3; dt++) {
        int tt = t + dt - 1;
        #pragma unroll
        for (int df = 0; df < 3; df++) {
            int ff = f + df - 1;
            in[dt][df] = (tt >= 0 && tt < TT && ff >= 0 && ff < FF) ? sp[tt*FF + ff] : 0.f;
        }
    }
    #pragma unroll
    for (int c = 0; c < C1N; c++) {
        float acc = 0.f;
        #pragma unroll
        for (int k9 = 0; k9 < 9; k9++)
            acc = fmaf(in[k9/3][k9%3], sw[c*9 + k9], acc);
        float val = acc * ssc[c] + sbi[c];
        g_y1[(((size_t)b*C1N + c)*TT + t)*FF + f] = fmaxf(val, 0.f);
    }
}

// ---------------- K2: conv2(5->5) + BN + ReLU + maxpool(W/2)  (R5 scalar) --
__global__ void k_conv2pool(const float* __restrict__ w, const float* __restrict__ cb,
                            const float* __restrict__ bg, const float* __restrict__ bbt,
                            const float* __restrict__ bm, const float* __restrict__ bv) {
    __shared__ float sw[C1N*C1N*9];
    __shared__ float ssc[C1N], sbi[C1N];
    for (int i = threadIdx.x; i < C1N*C1N*9; i += blockDim.x) sw[i] = w[i];
    if (threadIdx.x < C1N) {
        float sc = bg[threadIdx.x] * rsqrtf(bv[threadIdx.x] + BNEPS);
        ssc[threadIdx.x] = sc;
        sbi[threadIdx.x] = (cb[threadIdx.x] - bm[threadIdx.x]) * sc + bbt[threadIdx.x];
    }
    __syncthreads();
    int idx = blockIdx.x * blockDim.x + threadIdx.x;
    if (idx >= BB*TT*F2) return;
    int fp = idx % F2;
    int t = (idx / F2) % TT;
    int b = idx / (F2*TT);
    float acc0[C1N], acc1[C1N];
    #pragma unroll
    for (int c = 0; c < C1N; c++) { acc0[c] = 0.f; acc1[c] = 0.f; }
    #pragma unroll
    for (int ci = 0; ci < C1N; ci++) {
        const float* base = g_y1 + ((size_t)b*C1N + ci)*TT*FF;
        float patch[3][4];
        #pragma unroll
        for (int dt = 0; dt < 3; dt++) {
            int tt = t + dt - 1;
            #pragma unroll
            for (int df = 0; df < 4; df++) {
                int ff = 2*fp + df - 1;
                patch[dt][df] = (tt >= 0 && tt < TT && ff >= 0 && ff < FF) ? base[tt*FF + ff] : 0.f;
            }
        }
        #pragma unroll
        for (int co = 0; co < C1N; co++) {
            const float* wp = &sw[(co*C1N + ci)*9];
            #pragma unroll
            for (int dt = 0; dt < 3; dt++) {
                #pragma unroll
                for (int df = 0; df < 3; df++) {
                    float wv_ = wp[dt*3 + df];
                    acc0[co] = fmaf(patch[dt][df],     wv_, acc0[co]);
                    acc1[co] = fmaf(patch[dt][df + 1], wv_, acc1[co]);
                }
            }
        }
    }
    #pragma unroll
    for (int co = 0; co < C1N; co++) {
        float v0 = fmaxf(acc0[co]*ssc[co] + sbi[co], 0.f);
        float v1 = fmaxf(acc1[co]*ssc[co] + sbi[co], 0.f);
        g_y2[(((size_t)b*C1N + co)*TT + t)*F2 + fp] = fmaxf(v0, v1);
    }
}

// ---------------- K3: conv3(5->11) + BN + ReLU + maxpool + transpose (R5) --
__global__ void k_conv3pool(const float* __restrict__ w, const float* __restrict__ cb,
                            const float* __restrict__ bg, const float* __restrict__ bbt,
                            const float* __restrict__ bm, const float* __restrict__ bv) {
    __shared__ float sw[C2N*C1N*9];   // 495 floats
    __shared__ float ssc[C2N], sbi[C2N];
    for (int i = threadIdx.x; i < C2N*C1N*9; i += blockDim.x) sw[i] = w[i];
    if (threadIdx.x < C2N) {
        float sc = bg[threadIdx.x] * rsqrtf(bv[threadIdx.x] + BNEPS);
        ssc[threadIdx.x] = sc;
        sbi[threadIdx.x] = (cb[threadIdx.x] - bm[threadIdx.x]) * sc + bbt[threadIdx.x];
    }
    __syncthreads();
    int idx = blockIdx.x * blockDim.x + threadIdx.x;
    if (idx >= BB*TT*F3) return;
    int fp = idx % F3;
    int t = (idx / F3) % TT;
    int b = idx / (F3*TT);
    float acc0[C2N], acc1[C2N];
    #pragma unroll
    for (int c = 0; c < C2N; c++) { acc0[c] = 0.f; acc1[c] = 0.f; }
    #pragma unroll
    for (int ci = 0; ci < C1N; ci++) {
        const float* base = g_y2 + ((size_t)b*C1N + ci)*TT*F2;
        float patch[3][4];
        #pragma unroll
        for (int dt = 0; dt < 3; dt++) {
            int tt = t + dt - 1;
            #pragma unroll
            for (int df = 0; df < 4; df++) {
                int ff = 2*fp + df - 1;
                patch[dt][df] = (tt >= 0 && tt < TT && ff >= 0 && ff < F2) ? base[tt*F2 + ff] : 0.f;
            }
        }
        #pragma unroll
        for (int co = 0; co < C2N; co++) {
            const float* wp = &sw[(co*C1N + ci)*9];
            #pragma unroll
            for (int dt = 0; dt < 3; dt++) {
                #pragma unroll
                for (int df = 0; df < 3; df++) {
                    float wv_ = wp[dt*3 + df];
                    acc0[co] = fmaf(patch[dt][df],     wv_, acc0[co]);
                    acc1[co] = fmaf(patch[dt][df + 1], wv_, acc1[co]);
                }
            }
        }
    }
    size_t rowbase = ((size_t)b*TT + t)*FEATP;
    #pragma unroll
    for (int co = 0; co < C2N; co++) {
        float v0 = fmaxf(acc0[co]*ssc[co] + sbi[co], 0.f);
        float v1 = fmaxf(acc1[co]*ssc[co] + sbi[co], 0.f);
        g_x627[rowbase + co*F3 + fp] = fmaxf(v0, v1);
    }
    if (fp < FEATP - FEAT) g_x627[rowbase + FEAT + fp] = 0.f;
}

// ---------------- K4: fc GEMM (20480 x 640p) @ (640p x 88) + bias (R5) -----
__global__ __launch_bounds__(128) void k_fc(const float* __restrict__ bias) {
    __shared__ float sA[2][64][33];
    __shared__ float sW[2][OFN][33];
    const int m0 = blockIdx.x * 64;
    const int tid = threadIdx.x;
    const int tx = tid % 8;
    const int ty = tid / 8;

    float acc[4][11];
    #pragma unroll
    for (int r = 0; r < 4; r++)
        #pragma unroll
        for (int j = 0; j < 11; j++) acc[r][j] = 0.f;

    float4 pa[4];
    float4 pw[6];

    {
        #pragma unroll
        for (int u = 0; u < 4; u++) {
            int id = tid + 128*u, row = id >> 3, ks = id & 7;
            pa[u] = *(const float4*)(g_x627 + (size_t)(m0 + row)*FEATP + 4*ks);
        }
        #pragma unroll
        for (int u = 0; u < 6; u++) {
            int id = tid + 128*u;
            if (id < 704) {
                int row = id >> 3, ks = id & 7;
                pw[u] = *(const float4*)(g_wfc + (size_t)row*FEATP + 4*ks);
            }
        }
        #pragma unroll
        for (int u = 0; u < 4; u++) {
            int id = tid + 128*u, row = id >> 3, ks = id & 7;
            sA[0][row][4*ks+0] = pa[u].x; sA[0][row][4*ks+1] = pa[u].y;
            sA[0][row][4*ks+2] = pa[u].z; sA[0][row][4*ks+3] = pa[u].w;
        }
        #pragma unroll
        for (int u = 0; u < 6; u++) {
            int id = tid + 128*u;
            if (id < 704) {
                int row = id >> 3, ks = id & 7;
                sW[0][row][4*ks+0] = pw[u].x; sW[0][row][4*ks+1] = pw[u].y;
                sW[0][row][4*ks+2] = pw[u].z; sW[0][row][4*ks+3] = pw[u].w;
            }
        }
    }
    __syncthreads();

    const int NIT = FEATP / 32;   // 20
    for (int it = 0; it < NIT; it++) {
        const int buf = it & 1;
        if (it + 1 < NIT) {
            const int k0 = (it + 1) * 32;
            #pragma unroll
            for (int u = 0; u < 4; u++) {
                int id = tid + 128*u, row = id >> 3, ks = id & 7;
                pa[u] = *(const float4*)(g_x627 + (size_t)(m0 + row)*FEATP + k0 + 4*ks);
            }
            #pragma unroll
            for (int u = 0; u < 6; u++) {
                int id = tid + 128*u;
                if (id < 704) {
                    int row = id >> 3, ks = id & 7;
                    pw[u] = *(const float4*)(g_wfc + (size_t)row*FEATP + k0 + 4*ks);
                }
            }
        }
        #pragma unroll 8
        for (int kk = 0; kk < 32; kk++) {
            float a0 = sA[buf][4*ty+0][kk];
            float a1 = sA[buf][4*ty+1][kk];
            float a2 = sA[buf][4*ty+2][kk];
            float a3 = sA[buf][4*ty+3][kk];
            #pragma unroll
            for (int j = 0; j < 11; j++) {
                float wv_ = sW[buf][tx + 8*j][kk];
                acc[0][j] = fmaf(a0, wv_, acc[0][j]);
                acc[1][j] = fmaf(a1, wv_, acc[1][j]);
                acc[2][j] = fmaf(a2, wv_, acc[2][j]);
                acc[3][j] = fmaf(a3, wv_, acc[3][j]);
            }
        }
        if (it + 1 < NIT) {
            const int nb = buf ^ 1;
            #pragma unroll
            for (int u = 0; u < 4; u++) {
                int id = tid + 128*u, row = id >> 3, ks = id & 7;
                sA[nb][row][4*ks+0] = pa[u].x; sA[nb][row][4*ks+1] = pa[u].y;
                sA[nb][row][4*ks+2] = pa[u].z; sA[nb][row][4*ks+3] = pa[u].w;
            }
            #pragma unroll
            for (int u = 0; u < 6; u++) {
                int id = tid + 128*u;
                if (id < 704) {
                    int row = id >> 3, ks = id & 7;
                    sW[nb][row][4*ks+0] = pw[u].x; sW[nb][row][4*ks+1] = pw[u].y;
                    sW[nb][row][4*ks+2] = pw[u].z; sW[nb][row][4*ks+3] = pw[u].w;
                }
            }
        }
        __syncthreads();
    }

    #pragma unroll
    for (int j = 0; j < 11; j++) {
        float bj = bias[tx + 8*j];
        #pragma unroll
        for (int r = 0; r < 4; r++)
            g_x88[(size_t)(m0 + 4*ty + r)*OFN + tx + 8*j] = acc[r][j] + bj;
    }
}

// ---------------- K5: qkv GEMM (20480 x 88) @ (88 x 144)  (R5) -------------
__global__ void k_qkv(const float* __restrict__ wq, const float* __restrict__ wk,
                      const float* __restrict__ wv) {
    __shared__ float sA[32][45];
    __shared__ float sW[144][45];
    int m0 = blockIdx.x * 32;
    int tx = threadIdx.x % 16;
    int ty = threadIdx.x / 16;
    float acc[2][9];
    #pragma unroll
    for (int r = 0; r < 2; r++)
        #pragma unroll
        for (int j = 0; j < 9; j++) acc[r][j] = 0.f;

    for (int k0 = 0; k0 < OFN; k0 += 44) {
        for (int i = threadIdx.x; i < 32*44; i += 256) {
            int rr = i / 44, kk = i % 44;
            sA[rr][kk] = g_x88[(size_t)(m0 + rr)*OFN + k0 + kk];
        }
        for (int i = threadIdx.x; i < 144*44; i += 256) {
            int n = i / 44, kk = i % 44;
            int kg = k0 + kk;
            float val;
            if (n < 48)      val = wq[n*OFN + kg];
            else if (n < 96) val = wk[(n - 48)*OFN + kg];
            else             val = wv[(n - 96)*OFN + kg];
            sW[n][kk] = val;
        }
        __syncthreads();
        #pragma unroll 11
        for (int kk = 0; kk < 44; kk++) {
            float a0 = sA[2*ty][kk], a1 = sA[2*ty + 1][kk];
            #pragma unroll
            for (int j = 0; j < 9; j++) {
                float wv_ = sW[tx + 16*j][kk];
                acc[0][j] = fmaf(a0, wv_, acc[0][j]);
                acc[1][j] = fmaf(a1, wv_, acc[1][j]);
            }
        }
        __syncthreads();
    }
    #pragma unroll
    for (int r = 0; r < 2; r++)
        #pragma unroll
        for (int j = 0; j < 9; j++)
            g_qkv[(size_t)(m0 + 2*ty + r)*144 + tx + 16*j] = acc[r][j];
}

// ---------------- K6: sliding-window attention (TTILE=128) -----------------
// dynamic smem: ks[158][49] | vs[158][49] | srel[48*31]  = 16972 floats (67.9KB)
#define TTILE 128
#define HROWS (TTILE + 30)
#define ATTN_SM_FLOATS (HROWS*49*2 + MCN*KW)
#define ATTN_SM_BYTES  (ATTN_SM_FLOATS*4)
__global__ __launch_bounds__(256) void k_attn(const float* __restrict__ rel,
                                              float* __restrict__ a_out) {
    extern __shared__ float dsm[];
    float* ks   = dsm;                    // [HROWS][49]
    float* vs   = dsm + HROWS*49;         // [HROWS][49]
    float* srel = dsm + HROWS*49*2;       // [48*31]
    int b  = blockIdx.x / (TT / TTILE);
    int t0 = (blockIdx.x % (TT / TTILE)) * TTILE;

    for (int i = threadIdx.x; i < MCN*KW; i += 256) srel[i] = rel[i];
    for (int i = threadIdx.x; i < HROWS*MCN; i += 256) {
        int row = i / MCN, col = i % MCN;
        int t = t0 + row - PADW;
        float kv = 0.f, vv = 0.f;
        if (t >= 0 && t < TT) {
            const float* p = g_qkv + ((size_t)b*TT + t)*144;
            kv = p[48 + col];
            vv = p[96 + col];
        }
        ks[row*49 + col] = kv;
        vs[row*49 + col] = vv;
    }
    __syncthreads();

    for (int item = threadIdx.x; item < TTILE*GN; item += 256) {
        int g  = item % GN;
        int tl = item / GN;
        int t = t0 + tl;
        int gd = g * DH;
        const float* qp = g_qkv + ((size_t)b*TT + t)*144 + gd;
        float q0 = qp[0], q1 = qp[1], q2 = qp[2], q3 = qp[3], q4 = qp[4], q5 = qp[5];

        float e[KW];
        float emax = -1e30f;
        #pragma unroll
        for (int kk = 0; kk < KW; kk++) {
            const float* kr = &ks[(tl + kk)*49 + gd];
            float s;
            s =          q0 * (kr[0] + srel[(gd + 0)*KW + kk]);
            s = fmaf(q1, (kr[1] + srel[(gd + 1)*KW + kk]), s);
            s = fmaf(q2, (kr[2] + srel[(gd + 2)*KW + kk]), s);
            s = fmaf(q3, (kr[3] + srel[(gd + 3)*KW + kk]), s);
            s = fmaf(q4, (kr[4] + srel[(gd + 4)*KW + kk]), s);
            s = fmaf(q5, (kr[5] + srel[(gd + 5)*KW + kk]), s);
            e[kk] = s;
            emax = fmaxf(emax, s);
        }
        float sum = 0.f;
        #pragma unroll
        for (int kk = 0; kk < KW; kk++) {
            e[kk] = __expf(e[kk] - emax);
            sum += e[kk];
        }
        float inv = 1.f / sum;
        float o0 = 0.f, o1 = 0.f, o2 = 0.f, o3 = 0.f, o4 = 0.f, o5 = 0.f;
        float* ap = a_out + (((size_t)b*TT + t)*GN + g)*KW;
        #pragma unroll
        for (int kk = 0; kk < KW; kk++) {
            float p = e[kk] * inv;
            ap[kk] = p;
            const float* vr = &vs[(tl + kk)*49 + gd];
            o0 = fmaf(p, vr[0], o0);
            o1 = fmaf(p, vr[1], o1);
            o2 = fmaf(p, vr[2], o2);
            o3 = fmaf(p, vr[3], o3);
            o4 = fmaf(p, vr[4], o4);
            o5 = fmaf(p, vr[5], o5);
        }
        float* op = g_out48 + ((size_t)b*TT + t)*MCN + gd;
        op[0] = o0; op[1] = o1; op[2] = o2; op[3] = o3; op[4] = o4; op[5] = o5;
    }
}

// ---------------- K7: LayerNorm(48) + linear(48->88) + sigmoid -------------
// 64 rows per block (320 blocks): weight staging amortized 8x vs R5.
__global__ __launch_bounds__(256) void k_lnout(const float* __restrict__ lng,
                        const float* __restrict__ lnb,
                        const float* __restrict__ lw, const float* __restrict__ lb,
                        float* __restrict__ out) {
    __shared__ float slw[OFN*49];
    __shared__ float sh[8][MCN];
    __shared__ float sg[MCN], sb[MCN], slb[OFN];
    for (int i = threadIdx.x; i < OFN*MCN; i += 256) {
        int n = i / MCN, j = i % MCN;
        slw[n*49 + j] = lw[i];
    }
    if (threadIdx.x < MCN) { sg[threadIdx.x] = lng[threadIdx.x]; sb[threadIdx.x] = lnb[threadIdx.x]; }
    if (threadIdx.x < OFN) slb[threadIdx.x] = lb[threadIdx.x];
    __syncthreads();

    int warp = threadIdx.x / 32, lane = threadIdx.x % 32;
    #pragma unroll
    for (int pass = 0; pass < 8; pass++) {
        size_t row = (size_t)blockIdx.x * 64 + pass*8 + warp;
        const float* xp = g_out48 + row*MCN;
        float x0 = xp[lane];
        float x1 = (lane < 16) ? xp[lane + 32] : 0.f;
        float s  = x0 + x1;
        float s2 = x0*x0 + x1*x1;
        #pragma unroll
        for (int off = 16; off > 0; off >>= 1) {
            s  += __shfl_xor_sync(0xFFFFFFFFu, s,  off);
            s2 += __shfl_xor_sync(0xFFFFFFFFu, s2, off);
        }
        float mu = s * (1.f/48.f);
        float var = s2 * (1.f/48.f) - mu*mu;
        float rstd = rsqrtf(var + 1e-5f);
        sh[warp][lane] = (x0 - mu) * rstd * sg[lane] + sb[lane];
        if (lane < 16) sh[warp][lane + 32] = (x1 - mu) * rstd * sg[lane + 32] + sb[lane + 32];
        __syncwarp();

        #pragma unroll
        for (int jj = 0; jj < 3; jj++) {
            int n = lane + 32*jj;
            if (n < OFN) {
                float z = slb[n];
                #pragma unroll
                for (int j = 0; j < MCN; j++)
                    z = fmaf(sh[warp][j], slw[n*49 + j], z);
                out[row*OFN + n] = 1.f / (1.f + __expf(-z));
            }
        }
        __syncwarp();
    }
}

// ---------------- launch ---------------------------------------------------
extern "C" void kernel_launch(void* const* d_in, const int* in_sizes, int n_in,
                              void* d_out, int out_size) {
    const float* spec  = (const float*)d_in[0];
    const float* c1_w  = (const float*)d_in[1];
    const float* c1_b  = (const float*)d_in[2];
    const float* bn1_g = (const float*)d_in[3];
    const float* bn1_b = (const float*)d_in[4];
    const float* bn1_m = (const float*)d_in[5];
    const float* bn1_v = (const float*)d_in[6];
    const float* c2_w  = (const float*)d_in[7];
    const float* c2_b  = (const float*)d_in[8];
    const float* bn2_g = (const float*)d_in[9];
    const float* bn2_b = (const float*)d_in[10];
    const float* bn2_m = (const float*)d_in[11];
    const float* bn2_v = (const float*)d_in[12];
    const float* c3_w  = (const float*)d_in[13];
    const float* c3_b  = (const float*)d_in[14];
    const float* bn3_g = (const float*)d_in[15];
    const float* bn3_b = (const float*)d_in[16];
    const float* bn3_m = (const float*)d_in[17];
    const float* bn3_v = (const float*)d_in[18];
    const float* fc_w  = (const float*)d_in[19];
    const float* fc_b  = (const float*)d_in[20];
    const float* wq    = (const float*)d_in[21];
    const float* wk    = (const float*)d_in[22];
    const float* wv    = (const float*)d_in[23];
    const float* rel   = (const float*)d_in[24];
    const float* ln_g  = (const float*)d_in[25];
    const float* ln_b  = (const float*)d_in[26];
    const float* lin_w = (const float*)d_in[27];
    const float* lin_b = (const float*)d_in[28];

    float* out   = (float*)d_out;                 // frame_pred (B,T,88)
    float* a_out = out + FRAME_ELEMS;             // a (B,T,8,31)

    cudaFuncSetAttribute(k_attn, cudaFuncAttributeMaxDynamicSharedMemorySize,
                         ATTN_SM_BYTES);

    k_repack_w<<<(OFN*FEATP + 255)/256, 256>>>(fc_w);
    int n1 = BB*TT*FF;
    k_conv1<<<(n1 + 255)/256, 256>>>(spec, c1_w, c1_b, bn1_g, bn1_b, bn1_m, bn1_v);
    int n2 = BB*TT*F2;
    k_conv2pool<<<(n2 + 255)/256, 256>>>(c2_w, c2_b, bn2_g, bn2_b, bn2_m, bn2_v);
    int n3 = BB*TT*F3;
    k_conv3pool<<<(n3 + 255)/256, 256>>>(c3_w, c3_b, bn3_g, bn3_b, bn3_m, bn3_v);
    k_fc<<<(BB*TT)/64, 128>>>(fc_b);
    k_qkv<<<(BB*TT)/32, 256>>>(wq, wk, wv);
    k_attn<<<BB*(TT/TTILE), 256, ATTN_SM_BYTES>>>(rel, a_out);
    k_lnout<<<(BB*TT)/64, 256>>>(ln_g, ln_b, lin_w, lin_b, out);
}

// round 14
// speedup vs baseline: 1.2073x; 1.0201x over previous
#include <cuda_runtime.h>

#define BB 8
#define TT 2560
#define FF 229
#define C1N 5
#define C2N 11
#define F2 114
#define F3 57
#define FEAT 627       // C2N * F3
#define FEATP 640      // padded K for fc (float4-aligned)
#define OFN 88
#define MCN 48
#define GN 8
#define DH 6
#define KW 31
#define PADW 15
#define BNEPS 1e-5f
#define FRAME_ELEMS (BB*TT*OFN)

// ---------------- scratch (device globals; no allocation allowed) ----------
__device__ float g_y1[(size_t)BB*C1N*TT*FF];     // conv1 out  (B,C1,T,F)
__device__ float g_y2[(size_t)BB*C1N*TT*F2];     // conv2+pool (B,C1,T,F2)
__device__ float g_x627[(size_t)BB*TT*FEATP];    // conv3+pool, (B*T, 640) padded
__device__ float g_wfc[(size_t)OFN*FEATP];       // repacked fc_w (88, 640) padded
__device__ float g_x88[(size_t)BB*TT*OFN];       // fc out (B*T, 88)
__device__ float g_qkv[(size_t)BB*TT*144];       // q|k|v (B*T, 144)
__device__ float g_out48[(size_t)BB*TT*MCN];     // attention out (B*T, 48)

// ---------------- K0: repack fc weights into padded layout -----------------
__global__ void k_repack_w(const float* __restrict__ fw) {
    int idx = blockIdx.x * blockDim.x + threadIdx.x;
    if (idx >= OFN*FEATP) return;
    int n = idx / FEATP, k = idx % FEATP;
    g_wfc[idx] = (k < FEAT) ? fw[n*FEAT + k] : 0.f;
}

// ---------------- K1: conv1(1->5) + BN + ReLU ------------------------------
__global__ void k_conv1(const float* __restrict__ spec, const float* __restrict__ w,
                        const float* __restrict__ cb, const float* __restrict__ bg,
                        const float* __restrict__ bbt, const float* __restrict__ bm,
                        const float* __restrict__ bv) {
    __shared__ float sw[C1N*9];
    __shared__ float ssc[C1N], sbi[C1N];
    for (int i = threadIdx.x; i < C1N*9; i += blockDim.x) sw[i] = w[i];
    if (threadIdx.x < C1N) {
        float sc = bg[threadIdx.x] * rsqrtf(bv[threadIdx.x] + BNEPS);
        ssc[threadIdx.x] = sc;
        sbi[threadIdx.x] = (cb[threadIdx.x] - bm[threadIdx.x]) * sc + bbt[threadIdx.x];
    }
    __syncthreads();
    int idx = blockIdx.x * blockDim.x + threadIdx.x;
    if (idx >= BB*TT*FF) return;
    int f = idx % FF;
    int t = (idx / FF) % TT;
    int b = idx / (FF*TT);
    const float* sp = spec + (size_t)b * TT * FF;
    float in[3][3];
    #pragma unroll
    for (int dt = 0; dt < 3; dt++) {
        int tt = t + dt - 1;
        #pragma unroll
        for (int df = 0; df < 3; df++) {
            int ff = f + df - 1;
            in[dt][df] = (tt >= 0 && tt < TT && ff >= 0 && ff < FF) ? sp[tt*FF + ff] : 0.f;
        }
    }
    #pragma unroll
    for (int c = 0; c < C1N; c++) {
        float acc = 0.f;
        #pragma unroll
        for (int k9 = 0; k9 < 9; k9++)
            acc = fmaf(in[k9/3][k9%3], sw[c*9 + k9], acc);
        float val = acc * ssc[c] + sbi[c];
        g_y1[(((size_t)b*C1N + c)*TT + t)*FF + f] = fmaxf(val, 0.f);
    }
}

// ---------------- K2: conv2(5->5) + BN + ReLU + maxpool(W/2)  (R5 scalar) --
__global__ void k_conv2pool(const float* __restrict__ w, const float* __restrict__ cb,
                            const float* __restrict__ bg, const float* __restrict__ bbt,
                            const float* __restrict__ bm, const float* __restrict__ bv) {
    __shared__ float sw[C1N*C1N*9];
    __shared__ float ssc[C1N], sbi[C1N];
    for (int i = threadIdx.x; i < C1N*C1N*9; i += blockDim.x) sw[i] = w[i];
    if (threadIdx.x < C1N) {
        float sc = bg[threadIdx.x] * rsqrtf(bv[threadIdx.x] + BNEPS);
        ssc[threadIdx.x] = sc;
        sbi[threadIdx.x] = (cb[threadIdx.x] - bm[threadIdx.x]) * sc + bbt[threadIdx.x];
    }
    __syncthreads();
    int idx = blockIdx.x * blockDim.x + threadIdx.x;
    if (idx >= BB*TT*F2) return;
    int fp = idx % F2;
    int t = (idx / F2) % TT;
    int b = idx / (F2*TT);
    float acc0[C1N], acc1[C1N];
    #pragma unroll
    for (int c = 0; c < C1N; c++) { acc0[c] = 0.f; acc1[c] = 0.f; }
    #pragma unroll
    for (int ci = 0; ci < C1N; ci++) {
        const float* base = g_y1 + ((size_t)b*C1N + ci)*TT*FF;
        float patch[3][4];
        #pragma unroll
        for (int dt = 0; dt < 3; dt++) {
            int tt = t + dt - 1;
            #pragma unroll
            for (int df = 0; df < 4; df++) {
                int ff = 2*fp + df - 1;
                patch[dt][df] = (tt >= 0 && tt < TT && ff >= 0 && ff < FF) ? base[tt*FF + ff] : 0.f;
            }
        }
        #pragma unroll
        for (int co = 0; co < C1N; co++) {
            const float* wp = &sw[(co*C1N + ci)*9];
            #pragma unroll
            for (int dt = 0; dt < 3; dt++) {
                #pragma unroll
                for (int df = 0; df < 3; df++) {
                    float wv_ = wp[dt*3 + df];
                    acc0[co] = fmaf(patch[dt][df],     wv_, acc0[co]);
                    acc1[co] = fmaf(patch[dt][df + 1], wv_, acc1[co]);
                }
            }
        }
    }
    #pragma unroll
    for (int co = 0; co < C1N; co++) {
        float v0 = fmaxf(acc0[co]*ssc[co] + sbi[co], 0.f);
        float v1 = fmaxf(acc1[co]*ssc[co] + sbi[co], 0.f);
        g_y2[(((size_t)b*C1N + co)*TT + t)*F2 + fp] = fmaxf(v0, v1);
    }
}

// ---------------- K3: conv3(5->11) + BN + ReLU + maxpool + transpose (R5) --
__global__ void k_conv3pool(const float* __restrict__ w, const float* __restrict__ cb,
                            const float* __restrict__ bg, const float* __restrict__ bbt,
                            const float* __restrict__ bm, const float* __restrict__ bv) {
    __shared__ float sw[C2N*C1N*9];   // 495 floats
    __shared__ float ssc[C2N], sbi[C2N];
    for (int i = threadIdx.x; i < C2N*C1N*9; i += blockDim.x) sw[i] = w[i];
    if (threadIdx.x < C2N) {
        float sc = bg[threadIdx.x] * rsqrtf(bv[threadIdx.x] + BNEPS);
        ssc[threadIdx.x] = sc;
        sbi[threadIdx.x] = (cb[threadIdx.x] - bm[threadIdx.x]) * sc + bbt[threadIdx.x];
    }
    __syncthreads();
    int idx = blockIdx.x * blockDim.x + threadIdx.x;
    if (idx >= BB*TT*F3) return;
    int fp = idx % F3;
    int t = (idx / F3) % TT;
    int b = idx / (F3*TT);
    float acc0[C2N], acc1[C2N];
    #pragma unroll
    for (int c = 0; c < C2N; c++) { acc0[c] = 0.f; acc1[c] = 0.f; }
    #pragma unroll
    for (int ci = 0; ci < C1N; ci++) {
        const float* base = g_y2 + ((size_t)b*C1N + ci)*TT*F2;
        float patch[3][4];
        #pragma unroll
        for (int dt = 0; dt < 3; dt++) {
            int tt = t + dt - 1;
            #pragma unroll
            for (int df = 0; df < 4; df++) {
                int ff = 2*fp + df - 1;
                patch[dt][df] = (tt >= 0 && tt < TT && ff >= 0 && ff < F2) ? base[tt*F2 + ff] : 0.f;
            }
        }
        #pragma unroll
        for (int co = 0; co < C2N; co++) {
            const float* wp = &sw[(co*C1N + ci)*9];
            #pragma unroll
            for (int dt = 0; dt < 3; dt++) {
                #pragma unroll
                for (int df = 0; df < 3; df++) {
                    float wv_ = wp[dt*3 + df];
                    acc0[co] = fmaf(patch[dt][df],     wv_, acc0[co]);
                    acc1[co] = fmaf(patch[dt][df + 1], wv_, acc1[co]);
                }
            }
        }
    }
    size_t rowbase = ((size_t)b*TT + t)*FEATP;
    #pragma unroll
    for (int co = 0; co < C2N; co++) {
        float v0 = fmaxf(acc0[co]*ssc[co] + sbi[co], 0.f);
        float v1 = fmaxf(acc1[co]*ssc[co] + sbi[co], 0.f);
        g_x627[rowbase + co*F3 + fp] = fmaxf(v0, v1);
    }
    if (fp < FEATP - FEAT) g_x627[rowbase + FEAT + fp] = 0.f;
}

// ---------------- K4: fc GEMM (20480 x 640p) @ (640p x 88) + bias (R5) -----
__global__ __launch_bounds__(128) void k_fc(const float* __restrict__ bias) {
    __shared__ float sA[2][64][33];
    __shared__ float sW[2][OFN][33];
    const int m0 = blockIdx.x * 64;
    const int tid = threadIdx.x;
    const int tx = tid % 8;
    const int ty = tid / 8;

    float acc[4][11];
    #pragma unroll
    for (int r = 0; r < 4; r++)
        #pragma unroll
        for (int j = 0; j < 11; j++) acc[r][j] = 0.f;

    float4 pa[4];
    float4 pw[6];

    {
        #pragma unroll
        for (int u = 0; u < 4; u++) {
            int id = tid + 128*u, row = id >> 3, ks = id & 7;
            pa[u] = *(const float4*)(g_x627 + (size_t)(m0 + row)*FEATP + 4*ks);
        }
        #pragma unroll
        for (int u = 0; u < 6; u++) {
            int id = tid + 128*u;
            if (id < 704) {
                int row = id >> 3, ks = id & 7;
                pw[u] = *(const float4*)(g_wfc + (size_t)row*FEATP + 4*ks);
            }
        }
        #pragma unroll
        for (int u = 0; u < 4; u++) {
            int id = tid + 128*u, row = id >> 3, ks = id & 7;
            sA[0][row][4*ks+0] = pa[u].x; sA[0][row][4*ks+1] = pa[u].y;
            sA[0][row][4*ks+2] = pa[u].z; sA[0][row][4*ks+3] = pa[u].w;
        }
        #pragma unroll
        for (int u = 0; u < 6; u++) {
            int id = tid + 128*u;
            if (id < 704) {
                int row = id >> 3, ks = id & 7;
                sW[0][row][4*ks+0] = pw[u].x; sW[0][row][4*ks+1] = pw[u].y;
                sW[0][row][4*ks+2] = pw[u].z; sW[0][row][4*ks+3] = pw[u].w;
            }
        }
    }
    __syncthreads();

    const int NIT = FEATP / 32;   // 20
    for (int it = 0; it < NIT; it++) {
        const int buf = it & 1;
        if (it + 1 < NIT) {
            const int k0 = (it + 1) * 32;
            #pragma unroll
            for (int u = 0; u < 4; u++) {
                int id = tid + 128*u, row = id >> 3, ks = id & 7;
                pa[u] = *(const float4*)(g_x627 + (size_t)(m0 + row)*FEATP + k0 + 4*ks);
            }
            #pragma unroll
            for (int u = 0; u < 6; u++) {
                int id = tid + 128*u;
                if (id < 704) {
                    int row = id >> 3, ks = id & 7;
                    pw[u] = *(const float4*)(g_wfc + (size_t)row*FEATP + k0 + 4*ks);
                }
            }
        }
        #pragma unroll 8
        for (int kk = 0; kk < 32; kk++) {
            float a0 = sA[buf][4*ty+0][kk];
            float a1 = sA[buf][4*ty+1][kk];
            float a2 = sA[buf][4*ty+2][kk];
            float a3 = sA[buf][4*ty+3][kk];
            #pragma unroll
            for (int j = 0; j < 11; j++) {
                float wv_ = sW[buf][tx + 8*j][kk];
                acc[0][j] = fmaf(a0, wv_, acc[0][j]);
                acc[1][j] = fmaf(a1, wv_, acc[1][j]);
                acc[2][j] = fmaf(a2, wv_, acc[2][j]);
                acc[3][j] = fmaf(a3, wv_, acc[3][j]);
            }
        }
        if (it + 1 < NIT) {
            const int nb = buf ^ 1;
            #pragma unroll
            for (int u = 0; u < 4; u++) {
                int id = tid + 128*u, row = id >> 3, ks = id & 7;
                sA[nb][row][4*ks+0] = pa[u].x; sA[nb][row][4*ks+1] = pa[u].y;
                sA[nb][row][4*ks+2] = pa[u].z; sA[nb][row][4*ks+3] = pa[u].w;
            }
            #pragma unroll
            for (int u = 0; u < 6; u++) {
                int id = tid + 128*u;
                if (id < 704) {
                    int row = id >> 3, ks = id & 7;
                    sW[nb][row][4*ks+0] = pw[u].x; sW[nb][row][4*ks+1] = pw[u].y;
                    sW[nb][row][4*ks+2] = pw[u].z; sW[nb][row][4*ks+3] = pw[u].w;
                }
            }
        }
        __syncthreads();
    }

    #pragma unroll
    for (int j = 0; j < 11; j++) {
        float bj = bias[tx + 8*j];
        #pragma unroll
        for (int r = 0; r < 4; r++)
            g_x88[(size_t)(m0 + 4*ty + r)*OFN + tx + 8*j] = acc[r][j] + bj;
    }
}

// ---------------- K5: qkv GEMM (20480 x 88) @ (88 x 144)  (R5) -------------
__global__ void k_qkv(const float* __restrict__ wq, const float* __restrict__ wk,
                      const float* __restrict__ wv) {
    __shared__ float sA[32][45];
    __shared__ float sW[144][45];
    int m0 = blockIdx.x * 32;
    int tx = threadIdx.x % 16;
    int ty = threadIdx.x / 16;
    float acc[2][9];
    #pragma unroll
    for (int r = 0; r < 2; r++)
        #pragma unroll
        for (int j = 0; j < 9; j++) acc[r][j] = 0.f;

    for (int k0 = 0; k0 < OFN; k0 += 44) {
        for (int i = threadIdx.x; i < 32*44; i += 256) {
            int rr = i / 44, kk = i % 44;
            sA[rr][kk] = g_x88[(size_t)(m0 + rr)*OFN + k0 + kk];
        }
        for (int i = threadIdx.x; i < 144*44; i += 256) {
            int n = i / 44, kk = i % 44;
            int kg = k0 + kk;
            float val;
            if (n < 48)      val = wq[n*OFN + kg];
            else if (n < 96) val = wk[(n - 48)*OFN + kg];
            else             val = wv[(n - 96)*OFN + kg];
            sW[n][kk] = val;
        }
        __syncthreads();
        #pragma unroll 11
        for (int kk = 0; kk < 44; kk++) {
            float a0 = sA[2*ty][kk], a1 = sA[2*ty + 1][kk];
            #pragma unroll
            for (int j = 0; j < 9; j++) {
                float wv_ = sW[tx + 16*j][kk];
                acc[0][j] = fmaf(a0, wv_, acc[0][j]);
                acc[1][j] = fmaf(a1, wv_, acc[1][j]);
            }
        }
        __syncthreads();
    }
    #pragma unroll
    for (int r = 0; r < 2; r++)
        #pragma unroll
        for (int j = 0; j < 9; j++)
            g_qkv[(size_t)(m0 + 2*ty + r)*144 + tx + 16*j] = acc[r][j];
}

// ---------------- K6: sliding-window attention (R5, TTILE=64) --------------
#define TTILE 64
__global__ void k_attn(const float* __restrict__ rel, float* __restrict__ a_out) {
    __shared__ float ks[TTILE + 30][49];
    __shared__ float vs[TTILE + 30][49];
    __shared__ float srel[MCN*KW];
    int b  = blockIdx.x / (TT / TTILE);
    int t0 = (blockIdx.x % (TT / TTILE)) * TTILE;

    for (int i = threadIdx.x; i < MCN*KW; i += 256) srel[i] = rel[i];
    for (int i = threadIdx.x; i < (TTILE + 30)*MCN; i += 256) {
        int row = i / MCN, col = i % MCN;
        int t = t0 + row - PADW;
        float kv = 0.f, vv = 0.f;
        if (t >= 0 && t < TT) {
            const float* p = g_qkv + ((size_t)b*TT + t)*144;
            kv = p[48 + col];
            vv = p[96 + col];
        }
        ks[row][col] = kv;
        vs[row][col] = vv;
    }
    __syncthreads();

    for (int item = threadIdx.x; item < TTILE*GN; item += 256) {
        int g  = item % GN;
        int tl = item / GN;
        int t = t0 + tl;
        int gd = g * DH;
        const float* qp = g_qkv + ((size_t)b*TT + t)*144 + gd;
        float q0 = qp[0], q1 = qp[1], q2 = qp[2], q3 = qp[3], q4 = qp[4], q5 = qp[5];

        float e[KW];
        float emax = -1e30f;
        #pragma unroll
        for (int kk = 0; kk < KW; kk++) {
            float s;
            s =          q0 * (ks[tl + kk][gd + 0] + srel[(gd + 0)*KW + kk]);
            s = fmaf(q1, (ks[tl + kk][gd + 1] + srel[(gd + 1)*KW + kk]), s);
            s = fmaf(q2, (ks[tl + kk][gd + 2] + srel[(gd + 2)*KW + kk]), s);
            s = fmaf(q3, (ks[tl + kk][gd + 3] + srel[(gd + 3)*KW + kk]), s);
            s = fmaf(q4, (ks[tl + kk][gd + 4] + srel[(gd + 4)*KW + kk]), s);
            s = fmaf(q5, (ks[tl + kk][gd + 5] + srel[(gd + 5)*KW + kk]), s);
            e[kk] = s;
            emax = fmaxf(emax, s);
        }
        float sum = 0.f;
        #pragma unroll
        for (int kk = 0; kk < KW; kk++) {
            e[kk] = __expf(e[kk] - emax);
            sum += e[kk];
        }
        float inv = 1.f / sum;
        float o0 = 0.f, o1 = 0.f, o2 = 0.f, o3 = 0.f, o4 = 0.f, o5 = 0.f;
        float* ap = a_out + (((size_t)b*TT + t)*GN + g)*KW;
        #pragma unroll
        for (int kk = 0; kk < KW; kk++) {
            float p = e[kk] * inv;
            ap[kk] = p;
            o0 = fmaf(p, vs[tl + kk][gd + 0], o0);
            o1 = fmaf(p, vs[tl + kk][gd + 1], o1);
            o2 = fmaf(p, vs[tl + kk][gd + 2], o2);
            o3 = fmaf(p, vs[tl + kk][gd + 3], o3);
            o4 = fmaf(p, vs[tl + kk][gd + 4], o4);
            o5 = fmaf(p, vs[tl + kk][gd + 5], o5);
        }
        float* op = g_out48 + ((size_t)b*TT + t)*MCN + gd;
        op[0] = o0; op[1] = o1; op[2] = o2; op[3] = o3; op[4] = o4; op[5] = o5;
    }
}

// ---------------- K7: LayerNorm(48) + linear(48->88) + sigmoid -------------
// 64 rows per block (320 blocks): weight staging amortized 8x vs R5.
__global__ __launch_bounds__(256) void k_lnout(const float* __restrict__ lng,
                        const float* __restrict__ lnb,
                        const float* __restrict__ lw, const float* __restrict__ lb,
                        float* __restrict__ out) {
    __shared__ float slw[OFN*49];
    __shared__ float sh[8][MCN];
    __shared__ float sg[MCN], sb[MCN], slb[OFN];
    for (int i = threadIdx.x; i < OFN*MCN; i += 256) {
        int n = i / MCN, j = i % MCN;
        slw[n*49 + j] = lw[i];
    }
    if (threadIdx.x < MCN) { sg[threadIdx.x] = lng[threadIdx.x]; sb[threadIdx.x] = lnb[threadIdx.x]; }
    if (threadIdx.x < OFN) slb[threadIdx.x] = lb[threadIdx.x];
    __syncthreads();

    int warp = threadIdx.x / 32, lane = threadIdx.x % 32;
    #pragma unroll
    for (int pass = 0; pass < 8; pass++) {
        size_t row = (size_t)blockIdx.x * 64 + pass*8 + warp;
        const float* xp = g_out48 + row*MCN;
        float x0 = xp[lane];
        float x1 = (lane < 16) ? xp[lane + 32] : 0.f;
        float s  = x0 + x1;
        float s2 = x0*x0 + x1*x1;
        #pragma unroll
        for (int off = 16; off > 0; off >>= 1) {
            s  += __shfl_xor_sync(0xFFFFFFFFu, s,  off);
            s2 += __shfl_xor_sync(0xFFFFFFFFu, s2, off);
        }
        float mu = s * (1.f/48.f);
        float var = s2 * (1.f/48.f) - mu*mu;
        float rstd = rsqrtf(var + 1e-5f);
        sh[warp][lane] = (x0 - mu) * rstd * sg[lane] + sb[lane];
        if (lane < 16) sh[warp][lane + 32] = (x1 - mu) * rstd * sg[lane + 32] + sb[lane + 32];
        __syncwarp();

        #pragma unroll
        for (int jj = 0; jj < 3; jj++) {
            int n = lane + 32*jj;
            if (n < OFN) {
                float z = slb[n];
                #pragma unroll
                for (int j = 0; j < MCN; j++)
                    z = fmaf(sh[warp][j], slw[n*49 + j], z);
                out[row*OFN + n] = 1.f / (1.f + __expf(-z));
            }
        }
        __syncwarp();
    }
}

// ---------------- launch ---------------------------------------------------
extern "C" void kernel_launch(void* const* d_in, const int* in_sizes, int n_in,
                              void* d_out, int out_size) {
    const float* spec  = (const float*)d_in[0];
    const float* c1_w  = (const float*)d_in[1];
    const float* c1_b  = (const float*)d_in[2];
    const float* bn1_g = (const float*)d_in[3];
    const float* bn1_b = (const float*)d_in[4];
    const float* bn1_m = (const float*)d_in[5];
    const float* bn1_v = (const float*)d_in[6];
    const float* c2_w  = (const float*)d_in[7];
    const float* c2_b  = (const float*)d_in[8];
    const float* bn2_g = (const float*)d_in[9];
    const float* bn2_b = (const float*)d_in[10];
    const float* bn2_m = (const float*)d_in[11];
    const float* bn2_v = (const float*)d_in[12];
    const float* c3_w  = (const float*)d_in[13];
    const float* c3_b  = (const float*)d_in[14];
    const float* bn3_g = (const float*)d_in[15];
    const float* bn3_b = (const float*)d_in[16];
    const float* bn3_m = (const float*)d_in[17];
    const float* bn3_v = (const float*)d_in[18];
    const float* fc_w  = (const float*)d_in[19];
    const float* fc_b  = (const float*)d_in[20];
    const float* wq    = (const float*)d_in[21];
    const float* wk    = (const float*)d_in[22];
    const float* wv    = (const float*)d_in[23];
    const float* rel   = (const float*)d_in[24];
    const float* ln_g  = (const float*)d_in[25];
    const float* ln_b  = (const float*)d_in[26];
    const float* lin_w = (const float*)d_in[27];
    const float* lin_b = (const float*)d_in[28];

    float* out   = (float*)d_out;                 // frame_pred (B,T,88)
    float* a_out = out + FRAME_ELEMS;             // a (B,T,8,31)

    k_repack_w<<<(OFN*FEATP + 255)/256, 256>>>(fc_w);
    int n1 = BB*TT*FF;
    k_conv1<<<(n1 + 255)/256, 256>>>(spec, c1_w, c1_b, bn1_g, bn1_b, bn1_m, bn1_v);
    int n2 = BB*TT*F2;
    k_conv2pool<<<(n2 + 255)/256, 256>>>(c2_w, c2_b, bn2_g, bn2_b, bn2_m, bn2_v);
    int n3 = BB*TT*F3;
    k_conv3pool<<<(n3 + 255)/256, 256>>>(c3_w, c3_b, bn3_g, bn3_b, bn3_m, bn3_v);
    k_fc<<<(BB*TT)/64, 128>>>(fc_b);
    k_qkv<<<(BB*TT)/32, 256>>>(wq, wk, wv);
    k_attn<<<BB*(TT/TTILE), 256>>>(rel, a_out);
    k_lnout<<<(BB*TT)/64, 256>>>(ln_g, ln_b, lin_w, lin_b, out);
}